// round 1
// baseline (speedup 1.0000x reference)
#include <cuda_runtime.h>
#include <math.h>

#define NN 100000
#define EE 1600000
#define GG 64
#define HH 128
#define OUTC 10
#define BN_EPS 1e-5f
#define NB_SCAN 98   // ceil(100000/1024)

// ---------------- scratch (static device globals; no allocation) ----------------
__device__ __align__(256) float g_bufA[NN*HH];
__device__ __align__(256) float g_bufB[NN*HH];
__device__ __align__(256) float g_t1[NN*HH];
__device__ __align__(256) float g_agg[NN*HH];
__device__ int g_deg[NN];
__device__ int g_rowstart[NN+1];
__device__ int g_cursor[NN];
__device__ int g_csrsrc[EE];
__device__ int g_bsum[NB_SCAN];
__device__ int g_gstart[GG+1];
__device__ __align__(16) float g_scale[HH];
__device__ __align__(16) float g_shift[HH];
__device__ double g_colsum[HH];
__device__ double g_colsq[HH];
__device__ float g_poolA[GG*HH];
__device__ float g_poolB[GG*HH];
__device__ float g_V[GG*HH];

__device__ __forceinline__ const float* sel_in(const float* xp, int sel) {
    switch (sel) { case 0: return xp; case 1: return g_bufA; case 2: return g_bufB; default: return g_t1; }
}
__device__ __forceinline__ float* sel_out(int sel) {
    switch (sel) { case 1: return g_bufA; case 2: return g_bufB; default: return g_t1; }
}

// ---------------- CSR build ----------------
__global__ void k_zero_deg() {
    int i = blockIdx.x*blockDim.x + threadIdx.x;
    if (i < NN) g_deg[i] = 0;
}
__global__ void k_hist(const int* __restrict__ dst) {
    int e = blockIdx.x*blockDim.x + threadIdx.x;
    if (e < EE) atomicAdd(&g_deg[dst[e]], 1);
}
__global__ void k_scan1() {
    __shared__ int sm[1024];
    int tid = threadIdx.x;
    int i = blockIdx.x*1024 + tid;
    int v = (i < NN) ? g_deg[i] : 0;
    sm[tid] = v;
    __syncthreads();
    for (int off = 1; off < 1024; off <<= 1) {
        int t = (tid >= off) ? sm[tid-off] : 0;
        __syncthreads();
        sm[tid] += t;
        __syncthreads();
    }
    if (i < NN) g_rowstart[i] = sm[tid] - v;      // exclusive within block
    if (tid == 1023) g_bsum[blockIdx.x] = sm[1023];
}
__global__ void k_scan2() {
    if (threadIdx.x == 0) {
        int acc = 0;
        for (int b = 0; b < NB_SCAN; b++) { int t = g_bsum[b]; g_bsum[b] = acc; acc += t; }
    }
}
__global__ void k_scan3() {
    int i = blockIdx.x*blockDim.x + threadIdx.x;
    if (i < NN) {
        int v = g_rowstart[i] + g_bsum[i >> 10];
        g_rowstart[i] = v;
        g_cursor[i] = v;
    }
    if (i == 0) g_rowstart[NN] = EE;
}
__global__ void k_fill(const int* __restrict__ src, const int* __restrict__ dst) {
    int e = blockIdx.x*blockDim.x + threadIdx.x;
    if (e < EE) {
        int d = dst[e];
        int p = atomicAdd(&g_cursor[d], 1);
        g_csrsrc[p] = src[e];
    }
}
__global__ void k_gstart(const int* __restrict__ batch) {
    int t = threadIdx.x;
    if (t > GG) return;
    int lo = 0, hi = NN;
    while (lo < hi) { int mid = (lo+hi) >> 1; if (batch[mid] < t) lo = mid+1; else hi = mid; }
    g_gstart[t] = lo;
}

// ---------------- per-layer helpers ----------------
__global__ void k_init_affine() {
    int c = threadIdx.x;
    if (c < HH) { g_scale[c] = 1.f; g_shift[c] = 0.f; }
}
__global__ void k_zero_stats() {
    int c = threadIdx.x;
    if (c < HH) { g_colsum[c] = 0.0; g_colsq[c] = 0.0; }
}
__global__ void k_bnfinal(const float* __restrict__ gamma, const float* __restrict__ beta) {
    int c = threadIdx.x;
    if (c >= HH) return;
    double mu  = g_colsum[c] / (double)NN;
    double var = g_colsq[c] / (double)NN - mu*mu;
    if (var < 0.0) var = 0.0;
    float inv = rsqrtf((float)var + BN_EPS);
    float s = gamma[c] * inv;
    g_scale[c] = s;
    g_shift[c] = beta[c] - (float)mu * s;
}

// agg[n] = sum_{e: dst=n} affine(h[src_e])   — CSR gather, no atomics, 1 warp/node
__global__ void k_gather(const float* __restrict__ xp, int hsel) {
    int gw = (blockIdx.x*blockDim.x + threadIdx.x) >> 5;
    int lane = threadIdx.x & 31;
    if (gw >= NN) return;
    const float* h = sel_in(xp, hsel);
    int rs = g_rowstart[gw], re = g_rowstart[gw+1];
    float4 sc = ((const float4*)g_scale)[lane];
    float4 sh = ((const float4*)g_shift)[lane];
    const float4* h4 = (const float4*)h;
    float4 acc = make_float4(0.f, 0.f, 0.f, 0.f);
    for (int j = rs; j < re; j++) {
        int s = g_csrsrc[j];
        float4 v = h4[s*32 + lane];
        acc.x += v.x*sc.x + sh.x;
        acc.y += v.y*sc.y + sh.y;
        acc.z += v.z*sc.z + sh.z;
        acc.w += v.w*sc.w + sh.w;
    }
    ((float4*)g_agg)[gw*32 + lane] = acc;
}

// C[N,128] = relu(A @ W + b); FUSE_IN: A = affine(h) + agg; STATS: accumulate column sum/sumsq
template<bool FUSE_IN, bool STATS>
__global__ void __launch_bounds__(256) k_gemm(const float* __restrict__ xp, int aSel, int outSel,
                                              const float* __restrict__ W,
                                              const float* __restrict__ bias)
{
    __shared__ float As[16][132];
    __shared__ float Ws[16][128];
    const float* A = sel_in(xp, aSel);
    float* out = sel_out(outSel);
    const int tid = threadIdx.x;
    const int ty = tid >> 4;
    const int tx = tid & 15;
    const int rowbase = blockIdx.x * 128;
    float acc[8][8];
#pragma unroll
    for (int i = 0; i < 8; i++)
#pragma unroll
        for (int j = 0; j < 8; j++) acc[i][j] = 0.f;

    for (int k0 = 0; k0 < 128; k0 += 16) {
#pragma unroll
        for (int it = 0; it < 2; it++) {
            int idx = tid*2 + it;
            int r = idx >> 2;
            int q = idx & 3;
            int grow = rowbase + r;
            float4 v = make_float4(0.f, 0.f, 0.f, 0.f);
            if (grow < NN) {
                v = *(const float4*)&A[grow*128 + k0 + q*4];
                if (FUSE_IN) {
                    float4 sc = *(const float4*)&g_scale[k0 + q*4];
                    float4 sh = *(const float4*)&g_shift[k0 + q*4];
                    float4 a2 = *(const float4*)&g_agg[grow*128 + k0 + q*4];
                    v.x = v.x*sc.x + sh.x + a2.x;
                    v.y = v.y*sc.y + sh.y + a2.y;
                    v.z = v.z*sc.z + sh.z + a2.z;
                    v.w = v.w*sc.w + sh.w + a2.w;
                }
            }
            As[q*4+0][r] = v.x; As[q*4+1][r] = v.y; As[q*4+2][r] = v.z; As[q*4+3][r] = v.w;
        }
#pragma unroll
        for (int it = 0; it < 2; it++) {
            int idx = tid*2 + it;
            int k = idx >> 5;
            int n4 = idx & 31;
            *(float4*)&Ws[k][n4*4] = *(const float4*)&W[(k0+k)*128 + n4*4];
        }
        __syncthreads();
#pragma unroll
        for (int k = 0; k < 16; k++) {
            float a[8], w[8];
            *(float4*)&a[0] = *(const float4*)&As[k][ty*8];
            *(float4*)&a[4] = *(const float4*)&As[k][ty*8+4];
            *(float4*)&w[0] = *(const float4*)&Ws[k][tx*8];
            *(float4*)&w[4] = *(const float4*)&Ws[k][tx*8+4];
#pragma unroll
            for (int i = 0; i < 8; i++)
#pragma unroll
                for (int j = 0; j < 8; j++) acc[i][j] = fmaf(a[i], w[j], acc[i][j]);
        }
        __syncthreads();
    }

    float bv[8];
    *(float4*)&bv[0] = *(const float4*)&bias[tx*8];
    *(float4*)&bv[4] = *(const float4*)&bias[tx*8+4];
    float ls[8], lq[8];
#pragma unroll
    for (int j = 0; j < 8; j++) { ls[j] = 0.f; lq[j] = 0.f; }
#pragma unroll
    for (int i = 0; i < 8; i++) {
        int grow = rowbase + ty*8 + i;
        if (grow < NN) {
            float r[8];
#pragma unroll
            for (int j = 0; j < 8; j++) {
                float v = acc[i][j] + bv[j];
                r[j] = v > 0.f ? v : 0.f;
                if (STATS) { ls[j] += r[j]; lq[j] += r[j]*r[j]; }
            }
            *(float4*)&out[grow*128 + tx*8]     = *(float4*)&r[0];
            *(float4*)&out[grow*128 + tx*8 + 4] = *(float4*)&r[4];
        }
    }
    if (STATS) {
        float* red = &As[0][0];   // 2048 floats needed, 2112 available
#pragma unroll
        for (int j = 0; j < 8; j++) red[ty*128 + tx*8 + j] = ls[j];
        __syncthreads();
        if (ty == 0) {
#pragma unroll
            for (int j = 0; j < 8; j++) {
                float s = 0.f;
                for (int t = 0; t < 16; t++) s += red[t*128 + tx*8 + j];
                atomicAdd(&g_colsum[tx*8 + j], (double)s);
            }
        }
        __syncthreads();
#pragma unroll
        for (int j = 0; j < 8; j++) red[ty*128 + tx*8 + j] = lq[j];
        __syncthreads();
        if (ty == 0) {
#pragma unroll
            for (int j = 0; j < 8; j++) {
                float s = 0.f;
                for (int t = 0; t < 16; t++) s += red[t*128 + tx*8 + j];
                atomicAdd(&g_colsq[tx*8 + j], (double)s);
            }
        }
    }
}

// per-graph mean pool of affine(h); one block per graph
__global__ void k_pool(const float* __restrict__ xp, int hsel, int poolSel) {
    int g = blockIdx.x, c = threadIdx.x;
    const float* h = sel_in(xp, hsel);
    float* pool = poolSel ? g_poolB : g_poolA;
    int s = g_gstart[g], e = g_gstart[g+1];
    float sc = g_scale[c], sh = g_shift[c];
    float acc = 0.f;
    for (int n = s; n < e; n++) acc += h[n*128 + c]*sc + sh;
    float cnt = (float)(e - s);
    if (cnt < 1.f) cnt = 1.f;
    pool[g*128 + c] = acc / cnt;
}

// per-graph: V[g] = disc_w @ pool_x[g]; classifier head + log_softmax
__global__ void k_head1(const float* __restrict__ lin1_w, const float* __restrict__ lin1_b,
                        const float* __restrict__ lin2_w, const float* __restrict__ lin2_b,
                        const float* __restrict__ disc_w, float* __restrict__ outp)
{
    __shared__ float px[128];
    __shared__ float cat[256];
    __shared__ float h1[128];
    __shared__ float zz[OUTC];
    int g = blockIdx.x;
    int c = threadIdx.x;
    px[c] = g_poolB[g*128 + c];
    cat[c] = g_poolA[g*128 + c];
    cat[128 + c] = px[c];
    __syncthreads();
    // V[g][c] = sum_e disc_w[c][e] * px[e]
    float acc = 0.f;
    for (int e = 0; e < 128; e++) acc += disc_w[c*128 + e] * px[e];
    g_V[g*128 + c] = acc;
    // h1 = relu(cat @ lin1_w + lin1_b)
    float a2 = lin1_b[c];
    for (int k = 0; k < 256; k++) a2 += cat[k] * lin1_w[k*128 + c];
    h1[c] = a2 > 0.f ? a2 : 0.f;
    __syncthreads();
    if (c < OUTC) {
        float z = lin2_b[c];
        for (int k = 0; k < 128; k++) z += h1[k] * lin2_w[k*OUTC + c];
        zz[c] = z;
    }
    __syncthreads();
    if (c == 0) {
        float m = -1e30f;
        for (int o = 0; o < OUTC; o++) m = fmaxf(m, zz[o]);
        float s = 0.f;
        for (int o = 0; o < OUTC; o++) s += expf(zz[o] - m);
        float lse = logf(s) + m;
        for (int o = 0; o < OUTC; o++) outp[g*OUTC + o] = zz[o] - lse;
    }
}

// bilinear logits: one warp per (which, g)
__global__ void k_head2(const float* __restrict__ disc_b, float* __restrict__ outp) {
    int wid = (blockIdx.x*blockDim.x + threadIdx.x) >> 5;
    int lane = threadIdx.x & 31;
    if (wid >= 2*GG) return;
    int which = wid >> 6;
    int g = wid & 63;
    int gs = (which == 0) ? g : (g == 32 ? 30 : 63 - g);
    const float* a = &g_poolB[g*128];
    const float* v = &g_V[gs*128];
    float s = 0.f;
    for (int e = lane; e < 128; e += 32) s += a[e] * v[e];
#pragma unroll
    for (int off = 16; off > 0; off >>= 1) s += __shfl_down_sync(0xffffffffu, s, off);
    if (lane == 0) outp[GG*OUTC + which*GG + g] = s + disc_b[0];
}

// ---------------- launch ----------------
extern "C" void kernel_launch(void* const* d_in, const int* in_sizes, int n_in,
                              void* d_out, int out_size)
{
    (void)in_sizes; (void)n_in; (void)out_size;
    const float* x     = (const float*)d_in[0];
    const int*   ei    = (const int*)d_in[1];
    const int*   src   = ei;
    const int*   dst   = ei + EE;
    const int*   batch = (const int*)d_in[2];
    const float* W1a = (const float*)d_in[3];  const float* b1a = (const float*)d_in[4];
    const float* W2a = (const float*)d_in[5];  const float* b2a = (const float*)d_in[6];
    const float* ga  = (const float*)d_in[7];  const float* bta = (const float*)d_in[8];
    const float* W1b = (const float*)d_in[9];  const float* b1b = (const float*)d_in[10];
    const float* W2b = (const float*)d_in[11]; const float* b2b = (const float*)d_in[12];
    const float* gb  = (const float*)d_in[13]; const float* btb = (const float*)d_in[14];
    const float* lin1_w = (const float*)d_in[15]; const float* lin1_b = (const float*)d_in[16];
    const float* lin2_w = (const float*)d_in[17]; const float* lin2_b = (const float*)d_in[18];
    const float* disc_w = (const float*)d_in[19]; const float* disc_b = (const float*)d_in[20];
    float* outp = (float*)d_out;

    // CSR build (once per launch)
    k_zero_deg<<<(NN+255)/256, 256>>>();
    k_hist<<<(EE+255)/256, 256>>>(dst);
    k_scan1<<<NB_SCAN, 1024>>>();
    k_scan2<<<1, 32>>>();
    k_scan3<<<(NN+255)/256, 256>>>();
    k_fill<<<(EE+255)/256, 256>>>(src, dst);
    k_gstart<<<1, 96>>>(batch);

    const int gemm_blocks = (NN + 127) / 128;
    const int gather_blocks = (NN*32 + 255) / 256;

    for (int br = 0; br < 2; br++) {
        const float* W1 = br ? W1b : W1a;  const float* b1 = br ? b1b : b1a;
        const float* W2 = br ? W2b : W2a;  const float* b2 = br ? b2b : b2a;
        const float* gamma = br ? gb : ga; const float* beta = br ? btb : bta;
        int hsel[3]  = {0, 1, 2};   // x, bufA, bufB
        int outsel[3] = {1, 2, 1};  // bufA, bufB, bufA
        k_init_affine<<<1, 128>>>();
        for (int l = 0; l < 3; l++) {
            k_gather<<<gather_blocks, 256>>>(x, hsel[l]);
            k_gemm<true, false><<<gemm_blocks, 256>>>(x, hsel[l], 3, W1 + l*HH*HH, b1 + l*HH);
            k_zero_stats<<<1, 128>>>();
            k_gemm<false, true><<<gemm_blocks, 256>>>(x, 3, outsel[l], W2 + l*HH*HH, b2 + l*HH);
            k_bnfinal<<<1, 128>>>(gamma + l*HH, beta + l*HH);
        }
        k_pool<<<GG, 128>>>(x, 1 /* final h in bufA */, br);
    }

    k_head1<<<GG, 128>>>(lin1_w, lin1_b, lin2_w, lin2_b, disc_w, outp);
    k_head2<<<16, 256>>>(disc_b, outp);
}

// round 2
// speedup vs baseline: 1.1488x; 1.1488x over previous
#include <cuda_runtime.h>
#include <math.h>

#define NN 100000
#define EE 1600000
#define GG 64
#define HH 128
#define OUTC 10
#define BN_EPS 1e-5f
#define NB_SCAN 98   // ceil(100000/1024)

// ---------------- scratch (static device globals; no allocation) ----------------
__device__ __align__(256) float g_bufA[NN*HH];
__device__ __align__(256) float g_bufB[NN*HH];
__device__ __align__(256) float g_t1[NN*HH];
__device__ __align__(256) float g_t2[NN*HH];
__device__ __align__(256) float g_agg[NN*HH];
__device__ int g_deg[NN];
__device__ int g_rowstart[NN+1];
__device__ int g_cursor[NN];
__device__ int g_csrsrc[EE];
__device__ int g_bsum[NB_SCAN];
__device__ int g_gstart[GG+1];
__device__ __align__(16) float g_scale[2*HH];   // per-branch affine
__device__ __align__(16) float g_shift[2*HH];
__device__ double g_colsum[HH];
__device__ double g_colsq[HH];
__device__ float g_poolA[GG*HH];
__device__ float g_poolB[GG*HH];
__device__ float g_V[GG*HH];

__device__ __forceinline__ const float* sel_in(const float* xp, int sel) {
    switch (sel) { case 0: return xp; case 1: return g_bufA; case 2: return g_bufB;
                   case 4: return g_t2; default: return g_t1; }
}
__device__ __forceinline__ float* sel_out(int sel) {
    switch (sel) { case 1: return g_bufA; case 2: return g_bufB; case 4: return g_t2; default: return g_t1; }
}

// ---------------- packed f32x2 helpers ----------------
__device__ __forceinline__ unsigned long long pack2(float x, float y) {
    unsigned long long r;
    asm("mov.b64 %0, {%1, %2};" : "=l"(r) : "f"(x), "f"(y));
    return r;
}
__device__ __forceinline__ void ffma2(unsigned long long& d, unsigned long long a, unsigned long long b) {
    asm("fma.rn.f32x2 %0, %1, %2, %0;" : "+l"(d) : "l"(a), "l"(b));
}
__device__ __forceinline__ float2 unpack2(unsigned long long v) {
    float2 r;
    asm("mov.b64 {%0, %1}, %2;" : "=f"(r.x), "=f"(r.y) : "l"(v));
    return r;
}

// ---------------- CSR build ----------------
__global__ void k_zero_deg() {
    int i = blockIdx.x*blockDim.x + threadIdx.x;
    if (i < NN) g_deg[i] = 0;
}
__global__ void k_hist(const int* __restrict__ dst) {
    int e = blockIdx.x*blockDim.x + threadIdx.x;
    if (e < EE) atomicAdd(&g_deg[dst[e]], 1);
}
__global__ void k_scan1() {
    __shared__ int sm[1024];
    int tid = threadIdx.x;
    int i = blockIdx.x*1024 + tid;
    int v = (i < NN) ? g_deg[i] : 0;
    sm[tid] = v;
    __syncthreads();
    for (int off = 1; off < 1024; off <<= 1) {
        int t = (tid >= off) ? sm[tid-off] : 0;
        __syncthreads();
        sm[tid] += t;
        __syncthreads();
    }
    if (i < NN) g_rowstart[i] = sm[tid] - v;      // exclusive within block
    if (tid == 1023) g_bsum[blockIdx.x] = sm[1023];
}
__global__ void k_scan2() {
    __shared__ int sm[128];
    int t = threadIdx.x;
    int v = (t < NB_SCAN) ? g_bsum[t] : 0;
    sm[t] = v;
    __syncthreads();
    for (int off = 1; off < 128; off <<= 1) {
        int u = (t >= off) ? sm[t-off] : 0;
        __syncthreads();
        sm[t] += u;
        __syncthreads();
    }
    if (t < NB_SCAN) g_bsum[t] = sm[t] - v;       // exclusive
}
__global__ void k_scan3() {
    int i = blockIdx.x*blockDim.x + threadIdx.x;
    if (i < NN) {
        int v = g_rowstart[i] + g_bsum[i >> 10];
        g_rowstart[i] = v;
        g_cursor[i] = v;
    }
    if (i == 0) g_rowstart[NN] = EE;
}
__global__ void k_fill(const int* __restrict__ src, const int* __restrict__ dst) {
    int e = blockIdx.x*blockDim.x + threadIdx.x;
    if (e < EE) {
        int d = dst[e];
        int p = atomicAdd(&g_cursor[d], 1);
        g_csrsrc[p] = src[e];
    }
}
__global__ void k_gstart(const int* __restrict__ batch) {
    int t = threadIdx.x;
    if (t > GG) return;
    int lo = 0, hi = NN;
    while (lo < hi) { int mid = (lo+hi) >> 1; if (batch[mid] < t) lo = mid+1; else hi = mid; }
    g_gstart[t] = lo;
}

// ---------------- per-layer helpers ----------------
__global__ void k_init_affine() {
    int t = threadIdx.x;   // 256: both branches
    if (t < 2*HH) { g_scale[t] = 1.f; g_shift[t] = 0.f; }
}
__global__ void k_zero_stats() {
    int c = threadIdx.x;
    if (c < HH) { g_colsum[c] = 0.0; g_colsq[c] = 0.0; }
}
__global__ void k_bnfinal(const float* __restrict__ gamma, const float* __restrict__ beta, int br) {
    int c = threadIdx.x;
    if (c >= HH) return;
    double mu  = g_colsum[c] / (double)NN;
    double var = g_colsq[c] / (double)NN - mu*mu;
    if (var < 0.0) var = 0.0;
    float inv = rsqrtf((float)var + BN_EPS);
    float s = gamma[c] * inv;
    g_scale[br*HH + c] = s;
    g_shift[br*HH + c] = beta[c] - (float)mu * s;
}

// agg[n] = scale * (sum_{e: dst=n} h[src_e]) + deg*shift  — CSR gather, 1 warp/node
__global__ void k_gather(const float* __restrict__ xp, int hsel, int br) {
    int gw = (blockIdx.x*blockDim.x + threadIdx.x) >> 5;
    int lane = threadIdx.x & 31;
    if (gw >= NN) return;
    const float4* __restrict__ h4 = (const float4*)sel_in(xp, hsel);
    int rs = g_rowstart[gw], re = g_rowstart[gw+1];
    float4 acc = make_float4(0.f, 0.f, 0.f, 0.f);
    int j = rs;
    for (; j + 4 <= re; j += 4) {
        int s0 = g_csrsrc[j], s1 = g_csrsrc[j+1], s2 = g_csrsrc[j+2], s3 = g_csrsrc[j+3];
        float4 v0 = h4[s0*32 + lane];
        float4 v1 = h4[s1*32 + lane];
        float4 v2 = h4[s2*32 + lane];
        float4 v3 = h4[s3*32 + lane];
        acc.x += (v0.x + v1.x) + (v2.x + v3.x);
        acc.y += (v0.y + v1.y) + (v2.y + v3.y);
        acc.z += (v0.z + v1.z) + (v2.z + v3.z);
        acc.w += (v0.w + v1.w) + (v2.w + v3.w);
    }
    for (; j < re; j++) {
        int s = g_csrsrc[j];
        float4 v = h4[s*32 + lane];
        acc.x += v.x; acc.y += v.y; acc.z += v.z; acc.w += v.w;
    }
    float4 sc = ((const float4*)(g_scale + br*HH))[lane];
    float4 sh = ((const float4*)(g_shift + br*HH))[lane];
    float degf = (float)(re - rs);
    float4 o;
    o.x = acc.x*sc.x + degf*sh.x;
    o.y = acc.y*sc.y + degf*sh.y;
    o.z = acc.z*sc.z + degf*sh.z;
    o.w = acc.w*sc.w + degf*sh.w;
    ((float4*)g_agg)[gw*32 + lane] = o;
}

// C[N,128] = relu(A @ W + b); FUSE_IN: A = affine(h) + agg; STATS: column sum/sumsq
template<bool FUSE_IN, bool STATS>
__global__ void __launch_bounds__(256) k_gemm(const float* __restrict__ xp, int aSel, int outSel,
                                              const float* __restrict__ W,
                                              const float* __restrict__ bias, int br)
{
    __shared__ float As[16][132];
    __shared__ float Ws[16][128];
    const float* A = sel_in(xp, aSel);
    float* out = sel_out(outSel);
    const int tid = threadIdx.x;
    const int ty = tid >> 4;
    const int tx = tid & 15;
    const int rowbase = blockIdx.x * 128;
    unsigned long long acc2[4][8];   // [row-pair][col] packed f32x2 (x=row 2ii, y=row 2ii+1)
#pragma unroll
    for (int ii = 0; ii < 4; ii++)
#pragma unroll
        for (int j = 0; j < 8; j++) acc2[ii][j] = 0ull;

    for (int k0 = 0; k0 < 128; k0 += 16) {
#pragma unroll
        for (int it = 0; it < 2; it++) {
            int idx = tid*2 + it;
            int r = idx >> 2;
            int q = idx & 3;
            int grow = rowbase + r;
            float4 v = make_float4(0.f, 0.f, 0.f, 0.f);
            if (grow < NN) {
                v = *(const float4*)&A[grow*128 + k0 + q*4];
                if (FUSE_IN) {
                    float4 sc = *(const float4*)&g_scale[br*HH + k0 + q*4];
                    float4 sh = *(const float4*)&g_shift[br*HH + k0 + q*4];
                    float4 a2 = *(const float4*)&g_agg[grow*128 + k0 + q*4];
                    v.x = v.x*sc.x + sh.x + a2.x;
                    v.y = v.y*sc.y + sh.y + a2.y;
                    v.z = v.z*sc.z + sh.z + a2.z;
                    v.w = v.w*sc.w + sh.w + a2.w;
                }
            }
            As[q*4+0][r] = v.x; As[q*4+1][r] = v.y; As[q*4+2][r] = v.z; As[q*4+3][r] = v.w;
        }
#pragma unroll
        for (int it = 0; it < 2; it++) {
            int idx = tid*2 + it;
            int k = idx >> 5;
            int n4 = idx & 31;
            *(float4*)&Ws[k][n4*4] = *(const float4*)&W[(k0+k)*128 + n4*4];
        }
        __syncthreads();
#pragma unroll
        for (int k = 0; k < 16; k++) {
            unsigned long long a2[4];
#pragma unroll
            for (int ii = 0; ii < 4; ii++)
                a2[ii] = *(const unsigned long long*)&As[k][ty*8 + 2*ii];
            float w8[8];
            *(float4*)&w8[0] = *(const float4*)&Ws[k][tx*8];
            *(float4*)&w8[4] = *(const float4*)&Ws[k][tx*8+4];
#pragma unroll
            for (int j = 0; j < 8; j++) {
                unsigned long long wd = pack2(w8[j], w8[j]);
#pragma unroll
                for (int ii = 0; ii < 4; ii++) ffma2(acc2[ii][j], a2[ii], wd);
            }
        }
        __syncthreads();
    }

    float bv[8];
    *(float4*)&bv[0] = *(const float4*)&bias[tx*8];
    *(float4*)&bv[4] = *(const float4*)&bias[tx*8+4];
    float ls[8], lq[8];
#pragma unroll
    for (int j = 0; j < 8; j++) { ls[j] = 0.f; lq[j] = 0.f; }
#pragma unroll
    for (int ii = 0; ii < 4; ii++) {
        int grow0 = rowbase + ty*8 + 2*ii;
        float r0[8], r1[8];
#pragma unroll
        for (int j = 0; j < 8; j++) {
            float2 v = unpack2(acc2[ii][j]);
            float v0 = v.x + bv[j];
            float v1 = v.y + bv[j];
            r0[j] = v0 > 0.f ? v0 : 0.f;
            r1[j] = v1 > 0.f ? v1 : 0.f;
        }
        if (grow0 < NN) {
            if (STATS) {
#pragma unroll
                for (int j = 0; j < 8; j++) { ls[j] += r0[j]; lq[j] += r0[j]*r0[j]; }
            }
            *(float4*)&out[grow0*128 + tx*8]     = *(float4*)&r0[0];
            *(float4*)&out[grow0*128 + tx*8 + 4] = *(float4*)&r0[4];
        }
        if (grow0 + 1 < NN) {
            if (STATS) {
#pragma unroll
                for (int j = 0; j < 8; j++) { ls[j] += r1[j]; lq[j] += r1[j]*r1[j]; }
            }
            *(float4*)&out[(grow0+1)*128 + tx*8]     = *(float4*)&r1[0];
            *(float4*)&out[(grow0+1)*128 + tx*8 + 4] = *(float4*)&r1[4];
        }
    }
    if (STATS) {
        float* red = &As[0][0];   // 2048 floats needed, 2112 available
#pragma unroll
        for (int j = 0; j < 8; j++) red[ty*128 + tx*8 + j] = ls[j];
        __syncthreads();
        if (ty == 0) {
#pragma unroll
            for (int j = 0; j < 8; j++) {
                float s = 0.f;
                for (int t = 0; t < 16; t++) s += red[t*128 + tx*8 + j];
                atomicAdd(&g_colsum[tx*8 + j], (double)s);
            }
        }
        __syncthreads();
#pragma unroll
        for (int j = 0; j < 8; j++) red[ty*128 + tx*8 + j] = lq[j];
        __syncthreads();
        if (ty == 0) {
#pragma unroll
            for (int j = 0; j < 8; j++) {
                float s = 0.f;
                for (int t = 0; t < 16; t++) s += red[t*128 + tx*8 + j];
                atomicAdd(&g_colsq[tx*8 + j], (double)s);
            }
        }
    }
}

// per-graph mean pool of affine(h); one block per graph
__global__ void k_pool(const float* __restrict__ xp, int hsel, int br) {
    int g = blockIdx.x, c = threadIdx.x;
    const float* h = sel_in(xp, hsel);
    float* pool = br ? g_poolB : g_poolA;
    int s = g_gstart[g], e = g_gstart[g+1];
    float sc = g_scale[br*HH + c], sh = g_shift[br*HH + c];
    float acc = 0.f;
    for (int n = s; n < e; n++) acc += h[n*128 + c];
    float cnt = (float)(e - s);
    float cl = cnt < 1.f ? 1.f : cnt;
    pool[g*128 + c] = (acc*sc + cnt*sh) / cl;
}

// per-graph: V[g] = disc_w @ pool_x[g]; classifier head + log_softmax
__global__ void k_head1(const float* __restrict__ lin1_w, const float* __restrict__ lin1_b,
                        const float* __restrict__ lin2_w, const float* __restrict__ lin2_b,
                        const float* __restrict__ disc_w, float* __restrict__ outp)
{
    __shared__ float px[128];
    __shared__ float cat[256];
    __shared__ float h1[128];
    __shared__ float zz[OUTC];
    int g = blockIdx.x;
    int c = threadIdx.x;
    px[c] = g_poolB[g*128 + c];
    cat[c] = g_poolA[g*128 + c];
    cat[128 + c] = px[c];
    __syncthreads();
    float acc = 0.f;
    for (int e = 0; e < 128; e++) acc += disc_w[c*128 + e] * px[e];
    g_V[g*128 + c] = acc;
    float a2 = lin1_b[c];
    for (int k = 0; k < 256; k++) a2 += cat[k] * lin1_w[k*128 + c];
    h1[c] = a2 > 0.f ? a2 : 0.f;
    __syncthreads();
    if (c < OUTC) {
        float z = lin2_b[c];
        for (int k = 0; k < 128; k++) z += h1[k] * lin2_w[k*OUTC + c];
        zz[c] = z;
    }
    __syncthreads();
    if (c == 0) {
        float m = -1e30f;
        for (int o = 0; o < OUTC; o++) m = fmaxf(m, zz[o]);
        float s = 0.f;
        for (int o = 0; o < OUTC; o++) s += expf(zz[o] - m);
        float lse = logf(s) + m;
        for (int o = 0; o < OUTC; o++) outp[g*OUTC + o] = zz[o] - lse;
    }
}

// bilinear logits: one warp per (which, g)
__global__ void k_head2(const float* __restrict__ disc_b, float* __restrict__ outp) {
    int wid = (blockIdx.x*blockDim.x + threadIdx.x) >> 5;
    int lane = threadIdx.x & 31;
    if (wid >= 2*GG) return;
    int which = wid >> 6;
    int g = wid & 63;
    int gs = (which == 0) ? g : (g == 32 ? 30 : 63 - g);
    const float* a = &g_poolB[g*128];
    const float* v = &g_V[gs*128];
    float s = 0.f;
    for (int e = lane; e < 128; e += 32) s += a[e] * v[e];
#pragma unroll
    for (int off = 16; off > 0; off >>= 1) s += __shfl_down_sync(0xffffffffu, s, off);
    if (lane == 0) outp[GG*OUTC + which*GG + g] = s + disc_b[0];
}

// ---------------- launch ----------------
extern "C" void kernel_launch(void* const* d_in, const int* in_sizes, int n_in,
                              void* d_out, int out_size)
{
    (void)in_sizes; (void)n_in; (void)out_size;
    const float* x     = (const float*)d_in[0];
    const int*   ei    = (const int*)d_in[1];
    const int*   src   = ei;
    const int*   dst   = ei + EE;
    const int*   batch = (const int*)d_in[2];
    const float* W1a = (const float*)d_in[3];  const float* b1a = (const float*)d_in[4];
    const float* W2a = (const float*)d_in[5];  const float* b2a = (const float*)d_in[6];
    const float* ga  = (const float*)d_in[7];  const float* bta = (const float*)d_in[8];
    const float* W1b = (const float*)d_in[9];  const float* b1b = (const float*)d_in[10];
    const float* W2b = (const float*)d_in[11]; const float* b2b = (const float*)d_in[12];
    const float* gb  = (const float*)d_in[13]; const float* btb = (const float*)d_in[14];
    const float* lin1_w = (const float*)d_in[15]; const float* lin1_b = (const float*)d_in[16];
    const float* lin2_w = (const float*)d_in[17]; const float* lin2_b = (const float*)d_in[18];
    const float* disc_w = (const float*)d_in[19]; const float* disc_b = (const float*)d_in[20];
    float* outp = (float*)d_out;

    // CSR build (once per launch)
    k_zero_deg<<<(NN+255)/256, 256>>>();
    k_hist<<<(EE+255)/256, 256>>>(dst);
    k_scan1<<<NB_SCAN, 1024>>>();
    k_scan2<<<1, 128>>>();
    k_scan3<<<(NN+255)/256, 256>>>();
    k_fill<<<(EE+255)/256, 256>>>(src, dst);
    k_gstart<<<1, 96>>>(batch);

    const int gemm_blocks = (NN + 127) / 128;
    const int gather_blocks = (NN*32 + 255) / 256;

    k_init_affine<<<1, 256>>>();

    // ----- layer 1: shared gather of x (identity affine for both branches) -----
    k_gather<<<gather_blocks, 256>>>(x, 0, 0);
    // branch A layer 1
    k_gemm<true, false><<<gemm_blocks, 256>>>(x, 0, 3, W1a, b1a, 0);
    k_zero_stats<<<1, 128>>>();
    k_gemm<false, true><<<gemm_blocks, 256>>>(x, 3, 1, W2a, b2a, 0);
    k_bnfinal<<<1, 128>>>(ga, bta, 0);
    // branch B layer 1
    k_gemm<true, false><<<gemm_blocks, 256>>>(x, 0, 3, W1b, b1b, 1);
    k_zero_stats<<<1, 128>>>();
    k_gemm<false, true><<<gemm_blocks, 256>>>(x, 3, 2, W2b, b2b, 1);
    k_bnfinal<<<1, 128>>>(gb, btb, 1);

    // ----- branch A layers 2-3 -----
    k_gather<<<gather_blocks, 256>>>(x, 1, 0);
    k_gemm<true, false><<<gemm_blocks, 256>>>(x, 1, 3, W1a + 1*HH*HH, b1a + 1*HH, 0);
    k_zero_stats<<<1, 128>>>();
    k_gemm<false, true><<<gemm_blocks, 256>>>(x, 3, 4, W2a + 1*HH*HH, b2a + 1*HH, 0);
    k_bnfinal<<<1, 128>>>(ga + 1*HH, bta + 1*HH, 0);

    k_gather<<<gather_blocks, 256>>>(x, 4, 0);
    k_gemm<true, false><<<gemm_blocks, 256>>>(x, 4, 3, W1a + 2*HH*HH, b1a + 2*HH, 0);
    k_zero_stats<<<1, 128>>>();
    k_gemm<false, true><<<gemm_blocks, 256>>>(x, 3, 1, W2a + 2*HH*HH, b2a + 2*HH, 0);
    k_bnfinal<<<1, 128>>>(ga + 2*HH, bta + 2*HH, 0);
    k_pool<<<GG, 128>>>(x, 1, 0);

    // ----- branch B layers 2-3 -----
    k_gather<<<gather_blocks, 256>>>(x, 2, 1);
    k_gemm<true, false><<<gemm_blocks, 256>>>(x, 2, 3, W1b + 1*HH*HH, b1b + 1*HH, 1);
    k_zero_stats<<<1, 128>>>();
    k_gemm<false, true><<<gemm_blocks, 256>>>(x, 3, 4, W2b + 1*HH*HH, b2b + 1*HH, 1);
    k_bnfinal<<<1, 128>>>(gb + 1*HH, btb + 1*HH, 1);

    k_gather<<<gather_blocks, 256>>>(x, 4, 1);
    k_gemm<true, false><<<gemm_blocks, 256>>>(x, 4, 3, W1b + 2*HH*HH, b1b + 2*HH, 1);
    k_zero_stats<<<1, 128>>>();
    k_gemm<false, true><<<gemm_blocks, 256>>>(x, 3, 2, W2b + 2*HH*HH, b2b + 2*HH, 1);
    k_bnfinal<<<1, 128>>>(gb + 2*HH, btb + 2*HH, 1);
    k_pool<<<GG, 128>>>(x, 2, 1);

    // ----- heads -----
    k_head1<<<GG, 128>>>(lin1_w, lin1_b, lin2_w, lin2_b, disc_w, outp);
    k_head2<<<16, 256>>>(disc_b, outp);
}

// round 4
// speedup vs baseline: 1.3091x; 1.1395x over previous
#include <cuda_runtime.h>
#include <math.h>

#define NN 100000
#define EE 1600000
#define GG 64
#define HH 128
#define OUTC 10
#define BN_EPS 1e-5f
#define NB_SCAN 98   // ceil(100000/1024)
#define MT 64        // GEMM row tile

// ---------------- scratch (static device globals; no allocation) ----------------
__device__ __align__(256) float g_bufA[NN*HH];
__device__ __align__(256) float g_bufB[NN*HH];
__device__ __align__(256) float g_agg[NN*HH];
__device__ int g_deg[NN];
__device__ int g_rowstart[NN+1];
__device__ int g_cursor[NN];
__device__ int g_csrsrc[EE];
__device__ int g_bsum[NB_SCAN];
__device__ int g_gstart[GG+1];
__device__ __align__(16) float g_scale[3*HH];   // slot 0 = branch A, 1 = branch B, 2 = identity
__device__ __align__(16) float g_shift[3*HH];
__device__ double g_colsum[HH];
__device__ double g_colsq[HH];
__device__ float g_poolA[GG*HH];
__device__ float g_poolB[GG*HH];
__device__ float g_V[GG*HH];

__device__ __forceinline__ const float* sel_in(const float* xp, int sel) {
    switch (sel) { case 0: return xp; case 1: return g_bufA; default: return g_bufB; }
}
__device__ __forceinline__ float* sel_out(int sel) {
    return (sel == 1) ? g_bufA : g_bufB;
}

// ---------------- packed f32x2 helpers ----------------
__device__ __forceinline__ unsigned long long pack2(float x, float y) {
    unsigned long long r;
    asm("mov.b64 %0, {%1, %2};" : "=l"(r) : "f"(x), "f"(y));
    return r;
}
__device__ __forceinline__ void ffma2(unsigned long long& d, unsigned long long a, unsigned long long b) {
    asm("fma.rn.f32x2 %0, %1, %2, %0;" : "+l"(d) : "l"(a), "l"(b));
}
__device__ __forceinline__ float2 unpack2(unsigned long long v) {
    float2 r;
    asm("mov.b64 {%0, %1}, %2;" : "=f"(r.x), "=f"(r.y) : "l"(v));
    return r;
}

// ---------------- CSR build ----------------
__global__ void k_zero_deg() {
    int i = blockIdx.x*blockDim.x + threadIdx.x;
    if (i < NN) g_deg[i] = 0;
}
__global__ void k_hist(const int* __restrict__ dst) {
    int e = blockIdx.x*blockDim.x + threadIdx.x;
    if (e < EE) atomicAdd(&g_deg[dst[e]], 1);
}
__global__ void k_scan1() {
    __shared__ int sm[1024];
    int tid = threadIdx.x;
    int i = blockIdx.x*1024 + tid;
    int v = (i < NN) ? g_deg[i] : 0;
    sm[tid] = v;
    __syncthreads();
    for (int off = 1; off < 1024; off <<= 1) {
        int t = (tid >= off) ? sm[tid-off] : 0;
        __syncthreads();
        sm[tid] += t;
        __syncthreads();
    }
    if (i < NN) g_rowstart[i] = sm[tid] - v;
    if (tid == 1023) g_bsum[blockIdx.x] = sm[1023];
}
__global__ void k_scan2() {
    __shared__ int sm[128];
    int t = threadIdx.x;
    int v = (t < NB_SCAN) ? g_bsum[t] : 0;
    sm[t] = v;
    __syncthreads();
    for (int off = 1; off < 128; off <<= 1) {
        int u = (t >= off) ? sm[t-off] : 0;
        __syncthreads();
        sm[t] += u;
        __syncthreads();
    }
    if (t < NB_SCAN) g_bsum[t] = sm[t] - v;
}
__global__ void k_scan3() {
    int i = blockIdx.x*blockDim.x + threadIdx.x;
    if (i < NN) {
        int v = g_rowstart[i] + g_bsum[i >> 10];
        g_rowstart[i] = v;
        g_cursor[i] = v;
    }
    if (i == 0) g_rowstart[NN] = EE;
}
__global__ void k_fill(const int* __restrict__ src, const int* __restrict__ dst) {
    int e = blockIdx.x*blockDim.x + threadIdx.x;
    if (e < EE) {
        int d = dst[e];
        int p = atomicAdd(&g_cursor[d], 1);
        g_csrsrc[p] = src[e];
    }
}
__global__ void k_gstart(const int* __restrict__ batch) {
    int t = threadIdx.x;
    if (t > GG) return;
    int lo = 0, hi = NN;
    while (lo < hi) { int mid = (lo+hi) >> 1; if (batch[mid] < t) lo = mid+1; else hi = mid; }
    g_gstart[t] = lo;
}

// ---------------- per-layer helpers ----------------
__global__ void k_init_affine() {
    int t = threadIdx.x;   // 384: all 3 slots identity
    if (t < 3*HH) { g_scale[t] = 1.f; g_shift[t] = 0.f; }
}
__global__ void k_zero_stats() {
    int c = threadIdx.x;
    if (c < HH) { g_colsum[c] = 0.0; g_colsq[c] = 0.0; }
}
__global__ void k_bnfinal(const float* __restrict__ gamma, const float* __restrict__ beta, int br) {
    int c = threadIdx.x;
    if (c >= HH) return;
    double mu  = g_colsum[c] / (double)NN;
    double var = g_colsq[c] / (double)NN - mu*mu;
    if (var < 0.0) var = 0.0;
    float inv = rsqrtf((float)var + BN_EPS);
    float s = gamma[c] * inv;
    g_scale[br*HH + c] = s;
    g_shift[br*HH + c] = beta[c] - (float)mu * s;
    // re-zero for next layer (saves a separate launch)
    g_colsum[c] = 0.0;
    g_colsq[c] = 0.0;
}

// agg[n] = sc*(h[n] + sum_{e: dst=n} h[src_e]) + (deg+1)*sh  — complete MLP input
__global__ void k_gather(const float* __restrict__ xp, int hsel, int slot) {
    int gw = (blockIdx.x*blockDim.x + threadIdx.x) >> 5;
    int lane = threadIdx.x & 31;
    if (gw >= NN) return;
    const float4* __restrict__ h4 = (const float4*)sel_in(xp, hsel);
    int rs = g_rowstart[gw], re = g_rowstart[gw+1];
    float4 acc = h4[gw*32 + lane];   // self term
    int j = rs;
    for (; j + 4 <= re; j += 4) {
        int s0 = g_csrsrc[j], s1 = g_csrsrc[j+1], s2 = g_csrsrc[j+2], s3 = g_csrsrc[j+3];
        float4 v0 = h4[s0*32 + lane];
        float4 v1 = h4[s1*32 + lane];
        float4 v2 = h4[s2*32 + lane];
        float4 v3 = h4[s3*32 + lane];
        acc.x += (v0.x + v1.x) + (v2.x + v3.x);
        acc.y += (v0.y + v1.y) + (v2.y + v3.y);
        acc.z += (v0.z + v1.z) + (v2.z + v3.z);
        acc.w += (v0.w + v1.w) + (v2.w + v3.w);
    }
    for (; j < re; j++) {
        int s = g_csrsrc[j];
        float4 v = h4[s*32 + lane];
        acc.x += v.x; acc.y += v.y; acc.z += v.z; acc.w += v.w;
    }
    float4 sc = ((const float4*)(g_scale + slot*HH))[lane];
    float4 sh = ((const float4*)(g_shift + slot*HH))[lane];
    float cf = (float)(re - rs + 1);
    float4 o;
    o.x = acc.x*sc.x + cf*sh.x;
    o.y = acc.y*sc.y + cf*sh.y;
    o.z = acc.z*sc.z + cf*sh.z;
    o.w = acc.w*sc.w + cf*sh.w;
    ((float4*)g_agg)[gw*32 + lane] = o;
}

// Fused MLP: out = relu(relu(agg@W1+b1)@W2+b2), accumulate column stats of out.
// 64-row tiles, 128 threads, 8x8 frags, intermediate held in shared.
__global__ void __launch_bounds__(128, 3) k_mlp(int outSel,
                                                const float* __restrict__ W1, const float* __restrict__ b1,
                                                const float* __restrict__ W2, const float* __restrict__ b2)
{
    __shared__ float As[16][68];
    __shared__ float Ws[16][132];
    __shared__ float C1s[MT][132];
    float* out = sel_out(outSel);
    const int tid = threadIdx.x;
    const int ty = tid >> 4;      // 0..7 -> rows ty*8..ty*8+7
    const int tx = tid & 15;      // 0..15 -> cols tx*8..tx*8+7
    const int rowbase = blockIdx.x * MT;

    unsigned long long acc2[4][8];
#pragma unroll
    for (int ii = 0; ii < 4; ii++)
#pragma unroll
        for (int j = 0; j < 8; j++) acc2[ii][j] = 0ull;

    // ---------- GEMM1: C1 = relu(agg @ W1 + b1) ----------
    for (int k0 = 0; k0 < 128; k0 += 16) {
#pragma unroll
        for (int it = 0; it < 2; it++) {
            int idx = tid*2 + it;
            int r = idx >> 2;           // 0..63
            int q = idx & 3;
            int grow = rowbase + r;
            float4 v = make_float4(0.f, 0.f, 0.f, 0.f);
            if (grow < NN) v = *(const float4*)&g_agg[grow*128 + k0 + q*4];
            As[q*4+0][r] = v.x; As[q*4+1][r] = v.y; As[q*4+2][r] = v.z; As[q*4+3][r] = v.w;
        }
#pragma unroll
        for (int it = 0; it < 4; it++) {
            int idx = tid + it*128;
            int k = idx >> 5;
            int n4 = idx & 31;
            *(float4*)&Ws[k][n4*4] = *(const float4*)&W1[(k0+k)*128 + n4*4];
        }
        __syncthreads();
#pragma unroll
        for (int k = 0; k < 16; k++) {
            unsigned long long a2[4];
#pragma unroll
            for (int ii = 0; ii < 4; ii++)
                a2[ii] = *(const unsigned long long*)&As[k][ty*8 + 2*ii];
            float w8[8];
            *(float4*)&w8[0] = *(const float4*)&Ws[k][tx*8];
            *(float4*)&w8[4] = *(const float4*)&Ws[k][tx*8+4];
#pragma unroll
            for (int j = 0; j < 8; j++) {
                unsigned long long wd = pack2(w8[j], w8[j]);
#pragma unroll
                for (int ii = 0; ii < 4; ii++) ffma2(acc2[ii][j], a2[ii], wd);
            }
        }
        __syncthreads();
    }

    // epilogue 1: bias + relu -> C1s (row-major), reset acc
    {
        float bv[8];
        *(float4*)&bv[0] = *(const float4*)&b1[tx*8];
        *(float4*)&bv[4] = *(const float4*)&b1[tx*8+4];
#pragma unroll
        for (int ii = 0; ii < 4; ii++) {
            float r0[8], r1[8];
#pragma unroll
            for (int j = 0; j < 8; j++) {
                float2 v = unpack2(acc2[ii][j]);
                float v0 = v.x + bv[j];
                float v1 = v.y + bv[j];
                r0[j] = v0 > 0.f ? v0 : 0.f;
                r1[j] = v1 > 0.f ? v1 : 0.f;
                acc2[ii][j] = 0ull;
            }
            int rr = ty*8 + 2*ii;
            *(float4*)&C1s[rr][tx*8]     = *(float4*)&r0[0];
            *(float4*)&C1s[rr][tx*8+4]   = *(float4*)&r0[4];
            *(float4*)&C1s[rr+1][tx*8]   = *(float4*)&r1[0];
            *(float4*)&C1s[rr+1][tx*8+4] = *(float4*)&r1[4];
        }
    }
    __syncthreads();

    // ---------- GEMM2: out = relu(C1 @ W2 + b2) ----------
    for (int k0 = 0; k0 < 128; k0 += 16) {
#pragma unroll
        for (int it = 0; it < 4; it++) {
            int idx = tid + it*128;
            int k = idx >> 5;
            int n4 = idx & 31;
            *(float4*)&Ws[k][n4*4] = *(const float4*)&W2[(k0+k)*128 + n4*4];
        }
        __syncthreads();
#pragma unroll
        for (int k = 0; k < 16; k++) {
            int kk = k0 + k;
            float a[8];
#pragma unroll
            for (int i = 0; i < 8; i++) a[i] = C1s[ty*8 + i][kk];
            unsigned long long a2[4];
#pragma unroll
            for (int ii = 0; ii < 4; ii++) a2[ii] = pack2(a[2*ii], a[2*ii+1]);
            float w8[8];
            *(float4*)&w8[0] = *(const float4*)&Ws[k][tx*8];
            *(float4*)&w8[4] = *(const float4*)&Ws[k][tx*8+4];
#pragma unroll
            for (int j = 0; j < 8; j++) {
                unsigned long long wd = pack2(w8[j], w8[j]);
#pragma unroll
                for (int ii = 0; ii < 4; ii++) ffma2(acc2[ii][j], a2[ii], wd);
            }
        }
        __syncthreads();
    }

    // epilogue 2: bias + relu + store + column stats
    float bv[8];
    *(float4*)&bv[0] = *(const float4*)&b2[tx*8];
    *(float4*)&bv[4] = *(const float4*)&b2[tx*8+4];
    float ls[8], lq[8];
#pragma unroll
    for (int j = 0; j < 8; j++) { ls[j] = 0.f; lq[j] = 0.f; }
#pragma unroll
    for (int ii = 0; ii < 4; ii++) {
        int grow0 = rowbase + ty*8 + 2*ii;
        float r0[8], r1[8];
#pragma unroll
        for (int j = 0; j < 8; j++) {
            float2 v = unpack2(acc2[ii][j]);
            float v0 = v.x + bv[j];
            float v1 = v.y + bv[j];
            r0[j] = v0 > 0.f ? v0 : 0.f;
            r1[j] = v1 > 0.f ? v1 : 0.f;
        }
        if (grow0 < NN) {
#pragma unroll
            for (int j = 0; j < 8; j++) { ls[j] += r0[j]; lq[j] += r0[j]*r0[j]; }
            *(float4*)&out[grow0*128 + tx*8]     = *(float4*)&r0[0];
            *(float4*)&out[grow0*128 + tx*8 + 4] = *(float4*)&r0[4];
        }
        if (grow0 + 1 < NN) {
#pragma unroll
            for (int j = 0; j < 8; j++) { ls[j] += r1[j]; lq[j] += r1[j]*r1[j]; }
            *(float4*)&out[(grow0+1)*128 + tx*8]     = *(float4*)&r1[0];
            *(float4*)&out[(grow0+1)*128 + tx*8 + 4] = *(float4*)&r1[4];
        }
    }
    // block reduction over ty groups (8 x 128 floats in Ws space)
    float* red = &Ws[0][0];
#pragma unroll
    for (int j = 0; j < 8; j++) red[ty*128 + tx*8 + j] = ls[j];
    __syncthreads();
    {
        float s = 0.f;
#pragma unroll
        for (int t = 0; t < 8; t++) s += red[t*128 + tid];
        atomicAdd(&g_colsum[tid], (double)s);
    }
    __syncthreads();
#pragma unroll
    for (int j = 0; j < 8; j++) red[ty*128 + tx*8 + j] = lq[j];
    __syncthreads();
    {
        float s = 0.f;
#pragma unroll
        for (int t = 0; t < 8; t++) s += red[t*128 + tid];
        atomicAdd(&g_colsq[tid], (double)s);
    }
}

// per-graph mean pool of affine(h); one block per graph
__global__ void k_pool(const float* __restrict__ xp, int hsel, int br) {
    int g = blockIdx.x, c = threadIdx.x;
    const float* h = sel_in(xp, hsel);
    float* pool = br ? g_poolB : g_poolA;
    int s = g_gstart[g], e = g_gstart[g+1];
    float sc = g_scale[br*HH + c], sh = g_shift[br*HH + c];
    float acc = 0.f;
    for (int n = s; n < e; n++) acc += h[n*128 + c];
    float cnt = (float)(e - s);
    float cl = cnt < 1.f ? 1.f : cnt;
    pool[g*128 + c] = (acc*sc + cnt*sh) / cl;
}

// per-graph: V[g] = disc_w @ pool_x[g]; classifier head + log_softmax
__global__ void k_head1(const float* __restrict__ lin1_w, const float* __restrict__ lin1_b,
                        const float* __restrict__ lin2_w, const float* __restrict__ lin2_b,
                        const float* __restrict__ disc_w, float* __restrict__ outp)
{
    __shared__ float px[128];
    __shared__ float cat[256];
    __shared__ float h1[128];
    __shared__ float zz[OUTC];
    int g = blockIdx.x;
    int c = threadIdx.x;
    px[c] = g_poolB[g*128 + c];
    cat[c] = g_poolA[g*128 + c];
    cat[128 + c] = px[c];
    __syncthreads();
    float acc = 0.f;
    for (int e = 0; e < 128; e++) acc += disc_w[c*128 + e] * px[e];
    g_V[g*128 + c] = acc;
    float a2 = lin1_b[c];
    for (int k = 0; k < 256; k++) a2 += cat[k] * lin1_w[k*128 + c];
    h1[c] = a2 > 0.f ? a2 : 0.f;
    __syncthreads();
    if (c < OUTC) {
        float z = lin2_b[c];
        for (int k = 0; k < 128; k++) z += h1[k] * lin2_w[k*OUTC + c];
        zz[c] = z;
    }
    __syncthreads();
    if (c == 0) {
        float m = -1e30f;
        for (int o = 0; o < OUTC; o++) m = fmaxf(m, zz[o]);
        float s = 0.f;
        for (int o = 0; o < OUTC; o++) s += expf(zz[o] - m);
        float lse = logf(s) + m;
        for (int o = 0; o < OUTC; o++) outp[g*OUTC + o] = zz[o] - lse;
    }
}

// bilinear logits: one warp per (which, g)
__global__ void k_head2(const float* __restrict__ disc_b, float* __restrict__ outp) {
    int wid = (blockIdx.x*blockDim.x + threadIdx.x) >> 5;
    int lane = threadIdx.x & 31;
    if (wid >= 2*GG) return;
    int which = wid >> 6;
    int g = wid & 63;
    int gs = (which == 0) ? g : (g == 32 ? 30 : 63 - g);
    const float* a = &g_poolB[g*128];
    const float* v = &g_V[gs*128];
    float s = 0.f;
    for (int e = lane; e < 128; e += 32) s += a[e] * v[e];
#pragma unroll
    for (int off = 16; off > 0; off >>= 1) s += __shfl_down_sync(0xffffffffu, s, off);
    if (lane == 0) outp[GG*OUTC + which*GG + g] = s + disc_b[0];
}

// ---------------- launch ----------------
extern "C" void kernel_launch(void* const* d_in, const int* in_sizes, int n_in,
                              void* d_out, int out_size)
{
    (void)in_sizes; (void)n_in; (void)out_size;
    const float* x     = (const float*)d_in[0];
    const int*   ei    = (const int*)d_in[1];
    const int*   src   = ei;
    const int*   dst   = ei + EE;
    const int*   batch = (const int*)d_in[2];
    const float* W1a = (const float*)d_in[3];  const float* b1a = (const float*)d_in[4];
    const float* W2a = (const float*)d_in[5];  const float* b2a = (const float*)d_in[6];
    const float* ga  = (const float*)d_in[7];  const float* bta = (const float*)d_in[8];
    const float* W1b = (const float*)d_in[9];  const float* b1b = (const float*)d_in[10];
    const float* W2b = (const float*)d_in[11]; const float* b2b = (const float*)d_in[12];
    const float* gb  = (const float*)d_in[13]; const float* btb = (const float*)d_in[14];
    const float* lin1_w = (const float*)d_in[15]; const float* lin1_b = (const float*)d_in[16];
    const float* lin2_w = (const float*)d_in[17]; const float* lin2_b = (const float*)d_in[18];
    const float* disc_w = (const float*)d_in[19]; const float* disc_b = (const float*)d_in[20];
    float* outp = (float*)d_out;

    // CSR build (once per launch)
    k_zero_deg<<<(NN+255)/256, 256>>>();
    k_hist<<<(EE+255)/256, 256>>>(dst);
    k_scan1<<<NB_SCAN, 1024>>>();
    k_scan2<<<1, 128>>>();
    k_scan3<<<(NN+255)/256, 256>>>();
    k_fill<<<(EE+255)/256, 256>>>(src, dst);
    k_gstart<<<1, 96>>>(batch);

    const int mlp_blocks = (NN + MT - 1) / MT;
    const int gather_blocks = (NN*32 + 255) / 256;

    k_init_affine<<<1, 384>>>();
    k_zero_stats<<<1, 128>>>();

    // ----- layer 1: shared gather of x (identity affine, slot 2) -----
    k_gather<<<gather_blocks, 256>>>(x, 0, 2);
    k_mlp<<<mlp_blocks, 128>>>(1, W1a, b1a, W2a, b2a);
    k_bnfinal<<<1, 128>>>(ga, bta, 0);
    k_mlp<<<mlp_blocks, 128>>>(2, W1b, b1b, W2b, b2b);
    k_bnfinal<<<1, 128>>>(gb, btb, 1);

    // ----- branch A layers 2-3 -----
    k_gather<<<gather_blocks, 256>>>(x, 1, 0);
    k_mlp<<<mlp_blocks, 128>>>(1, W1a + 1*HH*HH, b1a + 1*HH, W2a + 1*HH*HH, b2a + 1*HH);
    k_bnfinal<<<1, 128>>>(ga + 1*HH, bta + 1*HH, 0);

    k_gather<<<gather_blocks, 256>>>(x, 1, 0);
    k_mlp<<<mlp_blocks, 128>>>(1, W1a + 2*HH*HH, b1a + 2*HH, W2a + 2*HH*HH, b2a + 2*HH);
    k_bnfinal<<<1, 128>>>(ga + 2*HH, bta + 2*HH, 0);
    k_pool<<<GG, 128>>>(x, 1, 0);

    // ----- branch B layers 2-3 -----
    k_gather<<<gather_blocks, 256>>>(x, 2, 1);
    k_mlp<<<mlp_blocks, 128>>>(2, W1b + 1*HH*HH, b1b + 1*HH, W2b + 1*HH*HH, b2b + 1*HH);
    k_bnfinal<<<1, 128>>>(gb + 1*HH, btb + 1*HH, 1);

    k_gather<<<gather_blocks, 256>>>(x, 2, 1);
    k_mlp<<<mlp_blocks, 128>>>(2, W1b + 2*HH*HH, b1b + 2*HH, W2b + 2*HH*HH, b2b + 2*HH);
    k_bnfinal<<<1, 128>>>(gb + 2*HH, btb + 2*HH, 1);
    k_pool<<<GG, 128>>>(x, 2, 1);

    // ----- heads -----
    k_head1<<<GG, 128>>>(lin1_w, lin1_b, lin2_w, lin2_b, disc_w, outp);
    k_head2<<<16, 256>>>(disc_b, outp);
}

// round 5
// speedup vs baseline: 1.4925x; 1.1401x over previous
#include <cuda_runtime.h>
#include <math.h>

#define NN 100000
#define EE 1600000
#define GG 64
#define HH 128
#define OUTC 10
#define BN_EPS 1e-5f
#define NB_SCAN 98   // ceil(100000/1024)
#define MT 64        // GEMM row tile

// ---------------- scratch (static device globals; no allocation) ----------------
__device__ __align__(256) float g_bufA[NN*HH];
__device__ __align__(256) float g_bufB[NN*HH];
__device__ __align__(256) float g_agg[2][NN*HH];
__device__ int g_deg[NN];
__device__ int g_rowstart[NN+1];
__device__ int g_cursor[NN];
__device__ int g_csrsrc[EE];
__device__ int g_bsum[NB_SCAN];
__device__ int g_gstart[GG+1];
__device__ __align__(16) float g_scale[3*HH];   // slot 0 = branch A, 1 = branch B, 2 = identity
__device__ __align__(16) float g_shift[3*HH];
__device__ double g_colsum[2*HH];
__device__ double g_colsq[2*HH];
__device__ float g_poolA[GG*HH];
__device__ float g_poolB[GG*HH];
__device__ float g_V[GG*HH];

// ---------------- packed f32x2 helpers ----------------
__device__ __forceinline__ unsigned long long pack2(float x, float y) {
    unsigned long long r;
    asm("mov.b64 %0, {%1, %2};" : "=l"(r) : "f"(x), "f"(y));
    return r;
}
__device__ __forceinline__ void ffma2(unsigned long long& d, unsigned long long a, unsigned long long b) {
    asm("fma.rn.f32x2 %0, %1, %2, %0;" : "+l"(d) : "l"(a), "l"(b));
}
__device__ __forceinline__ float2 unpack2(unsigned long long v) {
    float2 r;
    asm("mov.b64 {%0, %1}, %2;" : "=f"(r.x), "=f"(r.y) : "l"(v));
    return r;
}

// ---------------- CSR build ----------------
__global__ void k_zero_deg() {
    int i = blockIdx.x*blockDim.x + threadIdx.x;
    if (i < NN) g_deg[i] = 0;
}
__global__ void k_hist(const int* __restrict__ dst) {
    int e = blockIdx.x*blockDim.x + threadIdx.x;
    if (e < EE) atomicAdd(&g_deg[dst[e]], 1);
}
__global__ void k_scan1() {
    __shared__ int sm[1024];
    int tid = threadIdx.x;
    int i = blockIdx.x*1024 + tid;
    int v = (i < NN) ? g_deg[i] : 0;
    sm[tid] = v;
    __syncthreads();
    for (int off = 1; off < 1024; off <<= 1) {
        int t = (tid >= off) ? sm[tid-off] : 0;
        __syncthreads();
        sm[tid] += t;
        __syncthreads();
    }
    if (i < NN) g_rowstart[i] = sm[tid] - v;
    if (tid == 1023) g_bsum[blockIdx.x] = sm[1023];
}
__global__ void k_scan2() {
    __shared__ int sm[128];
    int t = threadIdx.x;
    int v = (t < NB_SCAN) ? g_bsum[t] : 0;
    sm[t] = v;
    __syncthreads();
    for (int off = 1; off < 128; off <<= 1) {
        int u = (t >= off) ? sm[t-off] : 0;
        __syncthreads();
        sm[t] += u;
        __syncthreads();
    }
    if (t < NB_SCAN) g_bsum[t] = sm[t] - v;
}
__global__ void k_scan3() {
    int i = blockIdx.x*blockDim.x + threadIdx.x;
    if (i < NN) {
        int v = g_rowstart[i] + g_bsum[i >> 10];
        g_rowstart[i] = v;
        g_cursor[i] = v;
    }
    if (i == 0) g_rowstart[NN] = EE;
}
__global__ void k_fill(const int* __restrict__ src, const int* __restrict__ dst) {
    int e = blockIdx.x*blockDim.x + threadIdx.x;
    if (e < EE) {
        int d = dst[e];
        int p = atomicAdd(&g_cursor[d], 1);
        g_csrsrc[p] = src[e];
    }
}
__global__ void k_gstart(const int* __restrict__ batch) {
    int t = threadIdx.x;
    if (t > GG) return;
    int lo = 0, hi = NN;
    while (lo < hi) { int mid = (lo+hi) >> 1; if (batch[mid] < t) lo = mid+1; else hi = mid; }
    g_gstart[t] = lo;
}

// ---------------- per-layer helpers ----------------
__global__ void k_init_affine() {
    int t = threadIdx.x;   // 384: all 3 slots identity
    if (t < 3*HH) { g_scale[t] = 1.f; g_shift[t] = 0.f; }
}
__global__ void k_zero_stats() {
    int c = threadIdx.x;   // 256
    g_colsum[c] = 0.0; g_colsq[c] = 0.0;
}
// both branches in one launch: 256 threads, br = t>>7
__global__ void k_bnfinal2(const float* __restrict__ gA, const float* __restrict__ btA,
                           const float* __restrict__ gB, const float* __restrict__ btB) {
    int t = threadIdx.x;
    int br = t >> 7, c = t & 127;
    const float* gamma = br ? gB : gA;
    const float* beta  = br ? btB : btA;
    double mu  = g_colsum[t] / (double)NN;
    double var = g_colsq[t] / (double)NN - mu*mu;
    if (var < 0.0) var = 0.0;
    float inv = rsqrtf((float)var + BN_EPS);
    float s = gamma[c] * inv;
    g_scale[br*HH + c] = s;
    g_shift[br*HH + c] = beta[c] - (float)mu * s;
    g_colsum[t] = 0.0;
    g_colsq[t] = 0.0;
}

// layer-1 gather of x (identity affine slot 2) -> agg slot 0
__global__ void k_gather1(const float* __restrict__ xp) {
    int gw = (blockIdx.x*blockDim.x + threadIdx.x) >> 5;
    int lane = threadIdx.x & 31;
    if (gw >= NN) return;
    const float4* __restrict__ h4 = (const float4*)xp;
    int rs = g_rowstart[gw], re = g_rowstart[gw+1];
    float4 acc = h4[gw*32 + lane];
    int j = rs;
    for (; j + 4 <= re; j += 4) {
        int s0 = g_csrsrc[j], s1 = g_csrsrc[j+1], s2 = g_csrsrc[j+2], s3 = g_csrsrc[j+3];
        float4 v0 = h4[s0*32 + lane];
        float4 v1 = h4[s1*32 + lane];
        float4 v2 = h4[s2*32 + lane];
        float4 v3 = h4[s3*32 + lane];
        acc.x += (v0.x + v1.x) + (v2.x + v3.x);
        acc.y += (v0.y + v1.y) + (v2.y + v3.y);
        acc.z += (v0.z + v1.z) + (v2.z + v3.z);
        acc.w += (v0.w + v1.w) + (v2.w + v3.w);
    }
    for (; j < re; j++) {
        int s = g_csrsrc[j];
        float4 v = h4[s*32 + lane];
        acc.x += v.x; acc.y += v.y; acc.z += v.z; acc.w += v.w;
    }
    ((float4*)g_agg[0])[gw*32 + lane] = acc;
}

// layers 2-3 gather, both branches in one launch (blockIdx.y = branch)
// agg[br][n] = sc_br*(h_br[n] + sum h_br[src]) + (deg+1)*sh_br
__global__ void k_gather2() {
    int gw = (blockIdx.x*blockDim.x + threadIdx.x) >> 5;
    int lane = threadIdx.x & 31;
    if (gw >= NN) return;
    int br = blockIdx.y;
    const float4* __restrict__ h4 = (const float4*)(br ? g_bufB : g_bufA);
    int rs = g_rowstart[gw], re = g_rowstart[gw+1];
    float4 acc = h4[gw*32 + lane];
    int j = rs;
    for (; j + 4 <= re; j += 4) {
        int s0 = g_csrsrc[j], s1 = g_csrsrc[j+1], s2 = g_csrsrc[j+2], s3 = g_csrsrc[j+3];
        float4 v0 = h4[s0*32 + lane];
        float4 v1 = h4[s1*32 + lane];
        float4 v2 = h4[s2*32 + lane];
        float4 v3 = h4[s3*32 + lane];
        acc.x += (v0.x + v1.x) + (v2.x + v3.x);
        acc.y += (v0.y + v1.y) + (v2.y + v3.y);
        acc.z += (v0.z + v1.z) + (v2.z + v3.z);
        acc.w += (v0.w + v1.w) + (v2.w + v3.w);
    }
    for (; j < re; j++) {
        int s = g_csrsrc[j];
        float4 v = h4[s*32 + lane];
        acc.x += v.x; acc.y += v.y; acc.z += v.z; acc.w += v.w;
    }
    float4 sc = ((const float4*)(g_scale + br*HH))[lane];
    float4 sh = ((const float4*)(g_shift + br*HH))[lane];
    float cf = (float)(re - rs + 1);
    float4 o;
    o.x = acc.x*sc.x + cf*sh.x;
    o.y = acc.y*sc.y + cf*sh.y;
    o.z = acc.z*sc.z + cf*sh.z;
    o.w = acc.w*sc.w + cf*sh.w;
    ((float4*)g_agg[br])[gw*32 + lane] = o;
}

// Fused MLP, both branches in one launch (blockIdx.y = branch).
// out_br = relu(relu(agg_br@W1+b1)@W2+b2), per-branch column stats.
__global__ void __launch_bounds__(128, 3) k_mlp2(int aggShared,
                                                 const float* __restrict__ W1A, const float* __restrict__ b1A,
                                                 const float* __restrict__ W2A, const float* __restrict__ b2A,
                                                 const float* __restrict__ W1B, const float* __restrict__ b1B,
                                                 const float* __restrict__ W2B, const float* __restrict__ b2B)
{
    __shared__ float As[16][68];
    __shared__ float Ws[16][132];
    __shared__ float C1t[128][70];   // [col][row], padded
    const int br = blockIdx.y;
    const float* W1 = br ? W1B : W1A;
    const float* b1 = br ? b1B : b1A;
    const float* W2 = br ? W2B : W2A;
    const float* b2 = br ? b2B : b2A;
    const float* Agg = g_agg[aggShared ? 0 : br];
    float* out = br ? g_bufB : g_bufA;
    const int tid = threadIdx.x;
    const int ty = tid >> 4;      // 0..7 -> rows ty*8..ty*8+7
    const int tx = tid & 15;      // 0..15 -> cols tx*8..tx*8+7
    const int rowbase = blockIdx.x * MT;

    unsigned long long acc2[4][8];
#pragma unroll
    for (int ii = 0; ii < 4; ii++)
#pragma unroll
        for (int j = 0; j < 8; j++) acc2[ii][j] = 0ull;

    // ---------- GEMM1: C1 = relu(agg @ W1 + b1) ----------
    for (int k0 = 0; k0 < 128; k0 += 16) {
#pragma unroll
        for (int it = 0; it < 2; it++) {
            int idx = tid*2 + it;
            int r = idx >> 2;           // 0..63
            int q = idx & 3;
            int grow = rowbase + r;
            float4 v = make_float4(0.f, 0.f, 0.f, 0.f);
            if (grow < NN) v = *(const float4*)&Agg[grow*128 + k0 + q*4];
            As[q*4+0][r] = v.x; As[q*4+1][r] = v.y; As[q*4+2][r] = v.z; As[q*4+3][r] = v.w;
        }
#pragma unroll
        for (int it = 0; it < 4; it++) {
            int idx = tid + it*128;
            int k = idx >> 5;
            int n4 = idx & 31;
            *(float4*)&Ws[k][n4*4] = *(const float4*)&W1[(k0+k)*128 + n4*4];
        }
        __syncthreads();
#pragma unroll
        for (int k = 0; k < 16; k++) {
            unsigned long long a2[4];
#pragma unroll
            for (int ii = 0; ii < 4; ii++)
                a2[ii] = *(const unsigned long long*)&As[k][ty*8 + 2*ii];
            float w8[8];
            *(float4*)&w8[0] = *(const float4*)&Ws[k][tx*8];
            *(float4*)&w8[4] = *(const float4*)&Ws[k][tx*8+4];
#pragma unroll
            for (int j = 0; j < 8; j++) {
                unsigned long long wd = pack2(w8[j], w8[j]);
#pragma unroll
                for (int ii = 0; ii < 4; ii++) ffma2(acc2[ii][j], a2[ii], wd);
            }
        }
        __syncthreads();
    }

    // epilogue 1: bias + relu -> C1t[col][row] (packed 64-bit row pairs), reset acc
    {
        float bv[8];
        *(float4*)&bv[0] = *(const float4*)&b1[tx*8];
        *(float4*)&bv[4] = *(const float4*)&b1[tx*8+4];
#pragma unroll
        for (int ii = 0; ii < 4; ii++) {
            int rr = ty*8 + 2*ii;
#pragma unroll
            for (int j = 0; j < 8; j++) {
                float2 v = unpack2(acc2[ii][j]);
                float v0 = v.x + bv[j];
                float v1 = v.y + bv[j];
                v0 = v0 > 0.f ? v0 : 0.f;
                v1 = v1 > 0.f ? v1 : 0.f;
                *(unsigned long long*)&C1t[tx*8+j][rr] = pack2(v0, v1);
                acc2[ii][j] = 0ull;
            }
        }
    }
    __syncthreads();

    // ---------- GEMM2: out = relu(C1 @ W2 + b2), A-frags broadcast from C1t ----------
    for (int k0 = 0; k0 < 128; k0 += 16) {
#pragma unroll
        for (int it = 0; it < 4; it++) {
            int idx = tid + it*128;
            int k = idx >> 5;
            int n4 = idx & 31;
            *(float4*)&Ws[k][n4*4] = *(const float4*)&W2[(k0+k)*128 + n4*4];
        }
        __syncthreads();
#pragma unroll
        for (int k = 0; k < 16; k++) {
            int kk = k0 + k;
            unsigned long long a2[4];
#pragma unroll
            for (int ii = 0; ii < 4; ii++)
                a2[ii] = *(const unsigned long long*)&C1t[kk][ty*8 + 2*ii];
            float w8[8];
            *(float4*)&w8[0] = *(const float4*)&Ws[k][tx*8];
            *(float4*)&w8[4] = *(const float4*)&Ws[k][tx*8+4];
#pragma unroll
            for (int j = 0; j < 8; j++) {
                unsigned long long wd = pack2(w8[j], w8[j]);
#pragma unroll
                for (int ii = 0; ii < 4; ii++) ffma2(acc2[ii][j], a2[ii], wd);
            }
        }
        __syncthreads();
    }

    // epilogue 2: bias + relu + store + per-branch column stats
    float bv[8];
    *(float4*)&bv[0] = *(const float4*)&b2[tx*8];
    *(float4*)&bv[4] = *(const float4*)&b2[tx*8+4];
    float ls[8], lq[8];
#pragma unroll
    for (int j = 0; j < 8; j++) { ls[j] = 0.f; lq[j] = 0.f; }
#pragma unroll
    for (int ii = 0; ii < 4; ii++) {
        int grow0 = rowbase + ty*8 + 2*ii;
        float r0[8], r1[8];
#pragma unroll
        for (int j = 0; j < 8; j++) {
            float2 v = unpack2(acc2[ii][j]);
            float v0 = v.x + bv[j];
            float v1 = v.y + bv[j];
            r0[j] = v0 > 0.f ? v0 : 0.f;
            r1[j] = v1 > 0.f ? v1 : 0.f;
        }
        if (grow0 < NN) {
#pragma unroll
            for (int j = 0; j < 8; j++) { ls[j] += r0[j]; lq[j] += r0[j]*r0[j]; }
            *(float4*)&out[grow0*128 + tx*8]     = *(float4*)&r0[0];
            *(float4*)&out[grow0*128 + tx*8 + 4] = *(float4*)&r0[4];
        }
        if (grow0 + 1 < NN) {
#pragma unroll
            for (int j = 0; j < 8; j++) { ls[j] += r1[j]; lq[j] += r1[j]*r1[j]; }
            *(float4*)&out[(grow0+1)*128 + tx*8]     = *(float4*)&r1[0];
            *(float4*)&out[(grow0+1)*128 + tx*8 + 4] = *(float4*)&r1[4];
        }
    }
    // block reduction over ty groups (8 x 128 floats in Ws space)
    float* red = &Ws[0][0];
#pragma unroll
    for (int j = 0; j < 8; j++) red[ty*128 + tx*8 + j] = ls[j];
    __syncthreads();
    {
        float s = 0.f;
#pragma unroll
        for (int t = 0; t < 8; t++) s += red[t*128 + tid];
        atomicAdd(&g_colsum[br*HH + tid], (double)s);
    }
    __syncthreads();
#pragma unroll
    for (int j = 0; j < 8; j++) red[ty*128 + tx*8 + j] = lq[j];
    __syncthreads();
    {
        float s = 0.f;
#pragma unroll
        for (int t = 0; t < 8; t++) s += red[t*128 + tid];
        atomicAdd(&g_colsq[br*HH + tid], (double)s);
    }
}

// per-graph mean pool of affine(h); one block per (graph, branch)
__global__ void k_pool2() {
    int g = blockIdx.x, br = blockIdx.y, c = threadIdx.x;
    const float* h = br ? g_bufB : g_bufA;
    float* pool = br ? g_poolB : g_poolA;
    int s = g_gstart[g], e = g_gstart[g+1];
    float sc = g_scale[br*HH + c], sh = g_shift[br*HH + c];
    float acc = 0.f;
    for (int n = s; n < e; n++) acc += h[n*128 + c];
    float cnt = (float)(e - s);
    float cl = cnt < 1.f ? 1.f : cnt;
    pool[g*128 + c] = (acc*sc + cnt*sh) / cl;
}

// per-graph: V[g] = disc_w @ pool_x[g]; classifier head + log_softmax
__global__ void k_head1(const float* __restrict__ lin1_w, const float* __restrict__ lin1_b,
                        const float* __restrict__ lin2_w, const float* __restrict__ lin2_b,
                        const float* __restrict__ disc_w, float* __restrict__ outp)
{
    __shared__ float px[128];
    __shared__ float cat[256];
    __shared__ float h1[128];
    __shared__ float zz[OUTC];
    int g = blockIdx.x;
    int c = threadIdx.x;
    px[c] = g_poolB[g*128 + c];
    cat[c] = g_poolA[g*128 + c];
    cat[128 + c] = px[c];
    __syncthreads();
    float acc = 0.f;
    for (int e = 0; e < 128; e++) acc += disc_w[c*128 + e] * px[e];
    g_V[g*128 + c] = acc;
    float a2 = lin1_b[c];
    for (int k = 0; k < 256; k++) a2 += cat[k] * lin1_w[k*128 + c];
    h1[c] = a2 > 0.f ? a2 : 0.f;
    __syncthreads();
    if (c < OUTC) {
        float z = lin2_b[c];
        for (int k = 0; k < 128; k++) z += h1[k] * lin2_w[k*OUTC + c];
        zz[c] = z;
    }
    __syncthreads();
    if (c == 0) {
        float m = -1e30f;
        for (int o = 0; o < OUTC; o++) m = fmaxf(m, zz[o]);
        float s = 0.f;
        for (int o = 0; o < OUTC; o++) s += expf(zz[o] - m);
        float lse = logf(s) + m;
        for (int o = 0; o < OUTC; o++) outp[g*OUTC + o] = zz[o] - lse;
    }
}

// bilinear logits: one warp per (which, g)
__global__ void k_head2(const float* __restrict__ disc_b, float* __restrict__ outp) {
    int wid = (blockIdx.x*blockDim.x + threadIdx.x) >> 5;
    int lane = threadIdx.x & 31;
    if (wid >= 2*GG) return;
    int which = wid >> 6;
    int g = wid & 63;
    int gs = (which == 0) ? g : (g == 32 ? 30 : 63 - g);
    const float* a = &g_poolB[g*128];
    const float* v = &g_V[gs*128];
    float s = 0.f;
    for (int e = lane; e < 128; e += 32) s += a[e] * v[e];
#pragma unroll
    for (int off = 16; off > 0; off >>= 1) s += __shfl_down_sync(0xffffffffu, s, off);
    if (lane == 0) outp[GG*OUTC + which*GG + g] = s + disc_b[0];
}

// ---------------- launch ----------------
extern "C" void kernel_launch(void* const* d_in, const int* in_sizes, int n_in,
                              void* d_out, int out_size)
{
    (void)in_sizes; (void)n_in; (void)out_size;
    const float* x     = (const float*)d_in[0];
    const int*   ei    = (const int*)d_in[1];
    const int*   src   = ei;
    const int*   dst   = ei + EE;
    const int*   batch = (const int*)d_in[2];
    const float* W1a = (const float*)d_in[3];  const float* b1a = (const float*)d_in[4];
    const float* W2a = (const float*)d_in[5];  const float* b2a = (const float*)d_in[6];
    const float* ga  = (const float*)d_in[7];  const float* bta = (const float*)d_in[8];
    const float* W1b = (const float*)d_in[9];  const float* b1b = (const float*)d_in[10];
    const float* W2b = (const float*)d_in[11]; const float* b2b = (const float*)d_in[12];
    const float* gb  = (const float*)d_in[13]; const float* btb = (const float*)d_in[14];
    const float* lin1_w = (const float*)d_in[15]; const float* lin1_b = (const float*)d_in[16];
    const float* lin2_w = (const float*)d_in[17]; const float* lin2_b = (const float*)d_in[18];
    const float* disc_w = (const float*)d_in[19]; const float* disc_b = (const float*)d_in[20];
    float* outp = (float*)d_out;

    // CSR build (once per launch)
    k_zero_deg<<<(NN+255)/256, 256>>>();
    k_hist<<<(EE+255)/256, 256>>>(dst);
    k_scan1<<<NB_SCAN, 1024>>>();
    k_scan2<<<1, 128>>>();
    k_scan3<<<(NN+255)/256, 256>>>();
    k_fill<<<(EE+255)/256, 256>>>(src, dst);
    k_gstart<<<1, 96>>>(batch);

    const int mlp_bx = (NN + MT - 1) / MT;
    const int gather_bx = (NN*32 + 255) / 256;
    const dim3 mlp_grid(mlp_bx, 2);
    const dim3 gather_grid(gather_bx, 2);

    k_init_affine<<<1, 384>>>();
    k_zero_stats<<<1, 256>>>();

    // ----- layer 1: single gather of x, both branch MLPs in one launch -----
    k_gather1<<<gather_bx, 256>>>(x);
    k_mlp2<<<mlp_grid, 128>>>(1, W1a, b1a, W2a, b2a, W1b, b1b, W2b, b2b);
    k_bnfinal2<<<1, 256>>>(ga, bta, gb, btb);

    // ----- layers 2-3: both branches per launch -----
    for (int l = 1; l < 3; l++) {
        k_gather2<<<gather_grid, 256>>>();
        k_mlp2<<<mlp_grid, 128>>>(0,
            W1a + l*HH*HH, b1a + l*HH, W2a + l*HH*HH, b2a + l*HH,
            W1b + l*HH*HH, b1b + l*HH, W2b + l*HH*HH, b2b + l*HH);
        k_bnfinal2<<<1, 256>>>(ga + l*HH, bta + l*HH, gb + l*HH, btb + l*HH);
    }

    k_pool2<<<dim3(GG, 2), 128>>>();

    // ----- heads -----
    k_head1<<<GG, 128>>>(lin1_w, lin1_b, lin2_w, lin2_b, disc_w, outp);
    k_head2<<<16, 256>>>(disc_b, outp);
}

// round 9
// speedup vs baseline: 1.9994x; 1.3397x over previous
#include <cuda_runtime.h>
#include <cuda_bf16.h>
#include <cstdint>
#include <math.h>

#define NN 100000
#define EE 1600000
#define GG 64
#define HH 128
#define OUTC 10
#define BN_EPS 1e-5f
#define NB_SCAN 98   // ceil(100000/1024)

// ---- k_mlp_mma smem layout (dynamic) ----
#define ASW 132                  // padded row stride in u32 words
#define AS_OFF 0                 // u32[128][132] : A as bf16 pairs (hi words 0-63, lo 64-127)
#define WS_OFF 67584             // u32[128][132] : W^T as bf16 pairs (hi|lo)
#define SB1_OFF 135168
#define SB2_OFF 135680
#define SMEM_BYTES 136192

// ---------------- scratch (static device globals; no allocation) ----------------
__device__ __align__(256) float g_bufA[NN*HH];
__device__ __align__(256) float g_bufB[NN*HH];
__device__ __align__(256) float g_agg[2][NN*HH];
// per mat (12): [n:128][256 bf16] : k 0-127 = hi, 128-255 = lo   (Wt[n][k] = W[k][n])
__device__ __align__(256) __nv_bfloat16 g_Wt[12*32768];
__device__ int g_deg[NN];
__device__ int g_rowstart[NN+1];
__device__ int g_cursor[NN];
__device__ int g_csrsrc[EE];
__device__ int g_bsum[NB_SCAN];
__device__ int g_gstart[GG+1];
__device__ __align__(16) float g_scale[3*HH];
__device__ __align__(16) float g_shift[3*HH];
__device__ double g_colsum[2*HH];
__device__ double g_colsq[2*HH];
__device__ float g_poolA[GG*HH];
__device__ float g_poolB[GG*HH];
__device__ float g_V[GG*HH];

// ---------------- mma helper ----------------
__device__ __forceinline__ void mma16816(float* dd, uint32_t a0, uint32_t a1, uint32_t a2, uint32_t a3,
                                         uint32_t b0, uint32_t b1) {
    asm volatile(
        "mma.sync.aligned.m16n8k16.row.col.f32.bf16.bf16.f32 "
        "{%0,%1,%2,%3}, {%4,%5,%6,%7}, {%8,%9}, {%0,%1,%2,%3};\n"
        : "+f"(dd[0]), "+f"(dd[1]), "+f"(dd[2]), "+f"(dd[3])
        : "r"(a0), "r"(a1), "r"(a2), "r"(a3), "r"(b0), "r"(b1));
}
__device__ __forceinline__ uint32_t bf16pair(float x, float y) {
    __nv_bfloat162 h = __float22bfloat162_rn(make_float2(x, y));
    return *(uint32_t*)&h;
}

// ---------------- CSR build ----------------
__global__ void k_zero_deg() {
    int i = blockIdx.x*blockDim.x + threadIdx.x;
    if (i < NN) g_deg[i] = 0;
}
__global__ void k_hist(const int* __restrict__ dst) {
    int e = blockIdx.x*blockDim.x + threadIdx.x;
    if (e < EE) atomicAdd(&g_deg[dst[e]], 1);
}
__global__ void k_scan1() {
    __shared__ int sm[1024];
    int tid = threadIdx.x;
    int i = blockIdx.x*1024 + tid;
    int v = (i < NN) ? g_deg[i] : 0;
    sm[tid] = v;
    __syncthreads();
    for (int off = 1; off < 1024; off <<= 1) {
        int t = (tid >= off) ? sm[tid-off] : 0;
        __syncthreads();
        sm[tid] += t;
        __syncthreads();
    }
    if (i < NN) g_rowstart[i] = sm[tid] - v;
    if (tid == 1023) g_bsum[blockIdx.x] = sm[1023];
}
__global__ void k_scan2() {
    __shared__ int sm[128];
    int t = threadIdx.x;
    int v = (t < NB_SCAN) ? g_bsum[t] : 0;
    sm[t] = v;
    __syncthreads();
    for (int off = 1; off < 128; off <<= 1) {
        int u = (t >= off) ? sm[t-off] : 0;
        __syncthreads();
        sm[t] += u;
        __syncthreads();
    }
    if (t < NB_SCAN) g_bsum[t] = sm[t] - v;
}
__global__ void k_scan3() {
    int i = blockIdx.x*blockDim.x + threadIdx.x;
    if (i < NN) {
        int v = g_rowstart[i] + g_bsum[i >> 10];
        g_rowstart[i] = v;
        g_cursor[i] = v;
    }
    if (i == 0) g_rowstart[NN] = EE;
}
__global__ void k_fill(const int* __restrict__ src, const int* __restrict__ dst) {
    int e = blockIdx.x*blockDim.x + threadIdx.x;
    if (e < EE) {
        int d = dst[e];
        int p = atomicAdd(&g_cursor[d], 1);
        g_csrsrc[p] = src[e];
    }
}
__global__ void k_gstart(const int* __restrict__ batch) {
    int t = threadIdx.x;
    if (t > GG) return;
    int lo = 0, hi = NN;
    while (lo < hi) { int mid = (lo+hi) >> 1; if (batch[mid] < t) lo = mid+1; else hi = mid; }
    g_gstart[t] = lo;
}

// ---------------- per-layer helpers ----------------
__global__ void k_init_affine() {
    int t = threadIdx.x;
    if (t < 3*HH) { g_scale[t] = 1.f; g_shift[t] = 0.f; }
}
__global__ void k_zero_stats() {
    int c = threadIdx.x;
    g_colsum[c] = 0.0; g_colsq[c] = 0.0;
}
__global__ void k_bnfinal2(const float* __restrict__ gA, const float* __restrict__ btA,
                           const float* __restrict__ gB, const float* __restrict__ btB) {
    int t = threadIdx.x;
    int br = t >> 7, c = t & 127;
    const float* gamma = br ? gB : gA;
    const float* beta  = br ? btB : btA;
    double mu  = g_colsum[t] / (double)NN;
    double var = g_colsq[t] / (double)NN - mu*mu;
    if (var < 0.0) var = 0.0;
    float inv = rsqrtf((float)var + BN_EPS);
    float s = gamma[c] * inv;
    g_scale[br*HH + c] = s;
    g_shift[br*HH + c] = beta[c] - (float)mu * s;
    g_colsum[t] = 0.0;
    g_colsq[t] = 0.0;
}

// convert all 12 W matrices to transposed/split bf16: g_Wt[mat][n][k(hi) | 128+k(lo)]
__global__ void k_wprep(const float* __restrict__ W1a, const float* __restrict__ W2a,
                        const float* __restrict__ W1b, const float* __restrict__ W2b) {
    int m = blockIdx.x*blockDim.x + threadIdx.x;
    if (m >= 12*16384) return;
    int mat = m >> 14;
    int elem = m & 16383;
    int k = elem >> 7, n = elem & 127;
    int br = mat / 6, rem = mat % 6, l = rem >> 1, g = rem & 1;
    const float* W = g ? (br ? W2b : W2a) : (br ? W1b : W1a);
    float w = W[l*16384 + k*128 + n];
    __nv_bfloat16 hi = __float2bfloat16(w);
    __nv_bfloat16 lo = __float2bfloat16(w - __bfloat162float(hi));
    g_Wt[mat*32768 + n*256 + k]       = hi;
    g_Wt[mat*32768 + n*256 + 128 + k] = lo;
}

// ---------------- gathers ----------------
__global__ void k_gather1(const float* __restrict__ xp) {
    int gw = (blockIdx.x*blockDim.x + threadIdx.x) >> 5;
    int lane = threadIdx.x & 31;
    if (gw >= NN) return;
    const float4* __restrict__ h4 = (const float4*)xp;
    int rs = g_rowstart[gw], re = g_rowstart[gw+1];
    float4 acc = h4[gw*32 + lane];
    int j = rs;
    for (; j + 4 <= re; j += 4) {
        int s0 = g_csrsrc[j], s1 = g_csrsrc[j+1], s2 = g_csrsrc[j+2], s3 = g_csrsrc[j+3];
        float4 v0 = h4[s0*32 + lane];
        float4 v1 = h4[s1*32 + lane];
        float4 v2 = h4[s2*32 + lane];
        float4 v3 = h4[s3*32 + lane];
        acc.x += (v0.x + v1.x) + (v2.x + v3.x);
        acc.y += (v0.y + v1.y) + (v2.y + v3.y);
        acc.z += (v0.z + v1.z) + (v2.z + v3.z);
        acc.w += (v0.w + v1.w) + (v2.w + v3.w);
    }
    for (; j < re; j++) {
        int s = g_csrsrc[j];
        float4 v = h4[s*32 + lane];
        acc.x += v.x; acc.y += v.y; acc.z += v.z; acc.w += v.w;
    }
    ((float4*)g_agg[0])[gw*32 + lane] = acc;
}
__global__ void k_gather2() {
    int gw = (blockIdx.x*blockDim.x + threadIdx.x) >> 5;
    int lane = threadIdx.x & 31;
    if (gw >= NN) return;
    int br = blockIdx.y;
    const float4* __restrict__ h4 = (const float4*)(br ? g_bufB : g_bufA);
    int rs = g_rowstart[gw], re = g_rowstart[gw+1];
    float4 acc = h4[gw*32 + lane];
    int j = rs;
    for (; j + 4 <= re; j += 4) {
        int s0 = g_csrsrc[j], s1 = g_csrsrc[j+1], s2 = g_csrsrc[j+2], s3 = g_csrsrc[j+3];
        float4 v0 = h4[s0*32 + lane];
        float4 v1 = h4[s1*32 + lane];
        float4 v2 = h4[s2*32 + lane];
        float4 v3 = h4[s3*32 + lane];
        acc.x += (v0.x + v1.x) + (v2.x + v3.x);
        acc.y += (v0.y + v1.y) + (v2.y + v3.y);
        acc.z += (v0.z + v1.z) + (v2.z + v3.z);
        acc.w += (v0.w + v1.w) + (v2.w + v3.w);
    }
    for (; j < re; j++) {
        int s = g_csrsrc[j];
        float4 v = h4[s*32 + lane];
        acc.x += v.x; acc.y += v.y; acc.z += v.z; acc.w += v.w;
    }
    float4 sc = ((const float4*)(g_scale + br*HH))[lane];
    float4 sh = ((const float4*)(g_shift + br*HH))[lane];
    float cf = (float)(re - rs + 1);
    float4 o;
    o.x = acc.x*sc.x + cf*sh.x;
    o.y = acc.y*sc.y + cf*sh.y;
    o.z = acc.z*sc.z + cf*sh.z;
    o.w = acc.w*sc.w + cf*sh.w;
    ((float4*)g_agg[br])[gw*32 + lane] = o;
}

// ---------------- HMMA fused MLP ----------------
// per block: 128 rows x 128 cols; out = relu(relu(agg@W1+b1)@W2+b2) via bf16 3-term mma.sync
__global__ void __launch_bounds__(256, 1)
k_mlp_mma(int aggShared, int layer,
          const float* __restrict__ b1a_, const float* __restrict__ b2a_,
          const float* __restrict__ b1b_, const float* __restrict__ b2b_)
{
    extern __shared__ char smem[];
    uint32_t* A32 = (uint32_t*)(smem + AS_OFF);
    uint32_t* W32 = (uint32_t*)(smem + WS_OFF);
    float* sb1 = (float*)(smem + SB1_OFF);
    float* sb2 = (float*)(smem + SB2_OFF);
    const int tid = threadIdx.x, wid = tid >> 5, lane = tid & 31;
    const int g = lane >> 2, t4 = lane & 3;
    const int br = blockIdx.y;
    const int rowbase = blockIdx.x * 128;
    const float* b1 = (br ? b1b_ : b1a_) + layer*HH;
    const float* b2 = (br ? b2b_ : b2a_) + layer*HH;
    const float* Agg = g_agg[aggShared ? 0 : br];
    float* out = br ? g_bufB : g_bufA;
    const __nv_bfloat16* Wt1 = &g_Wt[(br*6 + layer*2 + 0)*32768];
    const __nv_bfloat16* Wt2 = &g_Wt[(br*6 + layer*2 + 1)*32768];

    if (tid < 128) { sb1[tid] = b1[tid]; sb2[tid] = b2[tid]; }

    // stage W1: 128 rows x 32 uint4 per row (row n = 256 bf16 = 512 B), coalesced
    {
        const uint4* src = (const uint4*)Wt1;
#pragma unroll
        for (int i = 0; i < 16; i++) {
            int idx = tid + i*256;      // 0..4095
            int r = idx >> 5;           // row n
            int q = idx & 31;           // uint4 within row
            *(uint4*)&W32[r*ASW + q*4] = src[idx];
        }
    }
    // stage A: convert agg rows to bf16 hi/lo pairs (warp per row, coalesced)
#pragma unroll
    for (int i = 0; i < 16; i++) {
        int r = wid + 8*i;
        int grow = rowbase + r;
        float4 v = (grow < NN) ? ((const float4*)Agg)[grow*32 + lane] : make_float4(0.f,0.f,0.f,0.f);
        uint32_t h01 = bf16pair(v.x, v.y);
        uint32_t h23 = bf16pair(v.z, v.w);
        __nv_bfloat162 hb01 = *(__nv_bfloat162*)&h01;
        __nv_bfloat162 hb23 = *(__nv_bfloat162*)&h23;
        float2 f01 = __bfloat1622float2(hb01);
        float2 f23 = __bfloat1622float2(hb23);
        uint32_t l01 = bf16pair(v.x - f01.x, v.y - f01.y);
        uint32_t l23 = bf16pair(v.z - f23.x, v.w - f23.y);
        *(uint2*)&A32[r*ASW + lane*2]      = make_uint2(h01, h23);
        *(uint2*)&A32[r*ASW + 64 + lane*2] = make_uint2(l01, l23);
    }
    __syncthreads();

    const int abase[3] = {0, 64, 0};
    const int wbase[3] = {0, 0, 64};
    const int arow0 = (wid*16 + g)*ASW;
    const int arow1 = (wid*16 + g + 8)*ASW;

    float d[16][4];
#pragma unroll
    for (int nt = 0; nt < 16; nt++) { d[nt][0]=0.f; d[nt][1]=0.f; d[nt][2]=0.f; d[nt][3]=0.f; }

    // ---------- GEMM1 ----------
#pragma unroll
    for (int term = 0; term < 3; term++) {
#pragma unroll
        for (int s = 0; s < 8; s++) {
            int aw = abase[term] + s*8;
            int ww = wbase[term] + s*8;
            uint32_t a0 = A32[arow0 + aw + t4];
            uint32_t a1 = A32[arow1 + aw + t4];
            uint32_t a2 = A32[arow0 + aw + 4 + t4];
            uint32_t a3 = A32[arow1 + aw + 4 + t4];
#pragma unroll
            for (int nt = 0; nt < 16; nt++) {
                uint32_t b0 = W32[(nt*8+g)*ASW + ww + t4];
                uint32_t b1r = W32[(nt*8+g)*ASW + ww + 4 + t4];
                mma16816(d[nt], a0, a1, a2, a3, b0, b1r);
            }
        }
    }
    __syncthreads();   // all warps done reading W1

    // stage W2
    {
        const uint4* src = (const uint4*)Wt2;
#pragma unroll
        for (int i = 0; i < 16; i++) {
            int idx = tid + i*256;
            int r = idx >> 5;
            int q = idx & 31;
            *(uint4*)&W32[r*ASW + q*4] = src[idx];
        }
    }
    // epilogue 1: relu(d + b1) -> hi/lo bf16 back into own A rows
#pragma unroll
    for (int nt = 0; nt < 16; nt++) {
        int c = nt*8 + t4*2;
        float v0 = d[nt][0] + sb1[c];
        float v1 = d[nt][1] + sb1[c+1];
        float v2 = d[nt][2] + sb1[c];
        float v3 = d[nt][3] + sb1[c+1];
        v0 = v0 > 0.f ? v0 : 0.f;
        v1 = v1 > 0.f ? v1 : 0.f;
        v2 = v2 > 0.f ? v2 : 0.f;
        v3 = v3 > 0.f ? v3 : 0.f;
        uint32_t h0 = bf16pair(v0, v1);
        uint32_t h1 = bf16pair(v2, v3);
        float2 f0 = __bfloat1622float2(*(__nv_bfloat162*)&h0);
        float2 f1 = __bfloat1622float2(*(__nv_bfloat162*)&h1);
        uint32_t l0 = bf16pair(v0 - f0.x, v1 - f0.y);
        uint32_t l1 = bf16pair(v2 - f1.x, v3 - f1.y);
        int w = nt*4 + t4;
        A32[arow0 + w]      = h0;
        A32[arow0 + 64 + w] = l0;
        A32[arow1 + w]      = h1;
        A32[arow1 + 64 + w] = l1;
        d[nt][0]=0.f; d[nt][1]=0.f; d[nt][2]=0.f; d[nt][3]=0.f;
    }
    __syncthreads();   // W2 staged (A rows are warp-private)

    // ---------- GEMM2 ----------
#pragma unroll
    for (int term = 0; term < 3; term++) {
#pragma unroll
        for (int s = 0; s < 8; s++) {
            int aw = abase[term] + s*8;
            int ww = wbase[term] + s*8;
            uint32_t a0 = A32[arow0 + aw + t4];
            uint32_t a1 = A32[arow1 + aw + t4];
            uint32_t a2 = A32[arow0 + aw + 4 + t4];
            uint32_t a3 = A32[arow1 + aw + 4 + t4];
#pragma unroll
            for (int nt = 0; nt < 16; nt++) {
                uint32_t b0 = W32[(nt*8+g)*ASW + ww + t4];
                uint32_t b1r = W32[(nt*8+g)*ASW + ww + 4 + t4];
                mma16816(d[nt], a0, a1, a2, a3, b0, b1r);
            }
        }
    }

    // epilogue 2: relu(d + b2) -> fp32 into A region (zeros for padded rows)
    float* Af = (float*)(smem + AS_OFF);
    {
        int grow0 = rowbase + wid*16 + g;
        int grow1 = grow0 + 8;
#pragma unroll
        for (int nt = 0; nt < 16; nt++) {
            int c = nt*8 + t4*2;
            float v0 = d[nt][0] + sb2[c];
            float v1 = d[nt][1] + sb2[c+1];
            float v2 = d[nt][2] + sb2[c];
            float v3 = d[nt][3] + sb2[c+1];
            v0 = v0 > 0.f ? v0 : 0.f;
            v1 = v1 > 0.f ? v1 : 0.f;
            v2 = v2 > 0.f ? v2 : 0.f;
            v3 = v3 > 0.f ? v3 : 0.f;
            if (grow0 >= NN) { v0 = 0.f; v1 = 0.f; }
            if (grow1 >= NN) { v2 = 0.f; v3 = 0.f; }
            *(float2*)&Af[(wid*16+g)*ASW + c]   = make_float2(v0, v1);
            *(float2*)&Af[(wid*16+g+8)*ASW + c] = make_float2(v2, v3);
        }
    }
    __syncthreads();

    // per-column stats (2 threads per column, 64 rows each)
    {
        int col = tid & 127;
        int half = tid >> 7;
        float s = 0.f, q = 0.f;
#pragma unroll 8
        for (int r = half*64; r < half*64 + 64; r++) {
            float x = Af[r*ASW + col];
            s += x; q += x*x;
        }
        atomicAdd(&g_colsum[br*HH + col], (double)s);
        atomicAdd(&g_colsq[br*HH + col], (double)q);
    }
    // coalesced store (warp per row)
#pragma unroll
    for (int i = 0; i < 16; i++) {
        int r = wid + 8*i;
        int gr = rowbase + r;
        if (gr < NN) ((float4*)(out + gr*128))[lane] = *(const float4*)&Af[r*ASW + lane*4];
    }
}

// ---------------- pool & heads ----------------
__global__ void k_pool2() {
    int g = blockIdx.x, br = blockIdx.y, c = threadIdx.x;
    const float* h = br ? g_bufB : g_bufA;
    float* pool = br ? g_poolB : g_poolA;
    int s = g_gstart[g], e = g_gstart[g+1];
    float sc = g_scale[br*HH + c], sh = g_shift[br*HH + c];
    float acc = 0.f;
    for (int n = s; n < e; n++) acc += h[n*128 + c];
    float cnt = (float)(e - s);
    float cl = cnt < 1.f ? 1.f : cnt;
    pool[g*128 + c] = (acc*sc + cnt*sh) / cl;
}
__global__ void k_head1(const float* __restrict__ lin1_w, const float* __restrict__ lin1_b,
                        const float* __restrict__ lin2_w, const float* __restrict__ lin2_b,
                        const float* __restrict__ disc_w, float* __restrict__ outp)
{
    __shared__ float px[128];
    __shared__ float cat[256];
    __shared__ float h1[128];
    __shared__ float zz[OUTC];
    int g = blockIdx.x;
    int c = threadIdx.x;
    px[c] = g_poolB[g*128 + c];
    cat[c] = g_poolA[g*128 + c];
    cat[128 + c] = px[c];
    __syncthreads();
    float acc = 0.f;
    for (int e = 0; e < 128; e++) acc += disc_w[c*128 + e] * px[e];
    g_V[g*128 + c] = acc;
    float a2 = lin1_b[c];
    for (int k = 0; k < 256; k++) a2 += cat[k] * lin1_w[k*128 + c];
    h1[c] = a2 > 0.f ? a2 : 0.f;
    __syncthreads();
    if (c < OUTC) {
        float z = lin2_b[c];
        for (int k = 0; k < 128; k++) z += h1[k] * lin2_w[k*OUTC + c];
        zz[c] = z;
    }
    __syncthreads();
    if (c == 0) {
        float m = -1e30f;
        for (int o = 0; o < OUTC; o++) m = fmaxf(m, zz[o]);
        float s = 0.f;
        for (int o = 0; o < OUTC; o++) s += expf(zz[o] - m);
        float lse = logf(s) + m;
        for (int o = 0; o < OUTC; o++) outp[g*OUTC + o] = zz[o] - lse;
    }
}
__global__ void k_head2(const float* __restrict__ disc_b, float* __restrict__ outp) {
    int wid = (blockIdx.x*blockDim.x + threadIdx.x) >> 5;
    int lane = threadIdx.x & 31;
    if (wid >= 2*GG) return;
    int which = wid >> 6;
    int g = wid & 63;
    int gs = (which == 0) ? g : (g == 32 ? 30 : 63 - g);
    const float* a = &g_poolB[g*128];
    const float* v = &g_V[gs*128];
    float s = 0.f;
    for (int e = lane; e < 128; e += 32) s += a[e] * v[e];
#pragma unroll
    for (int off = 16; off > 0; off >>= 1) s += __shfl_down_sync(0xffffffffu, s, off);
    if (lane == 0) outp[GG*OUTC + which*GG + g] = s + disc_b[0];
}

// ---------------- launch ----------------
extern "C" void kernel_launch(void* const* d_in, const int* in_sizes, int n_in,
                              void* d_out, int out_size)
{
    (void)in_sizes; (void)n_in; (void)out_size;
    const float* x     = (const float*)d_in[0];
    const int*   ei    = (const int*)d_in[1];
    const int*   src   = ei;
    const int*   dst   = ei + EE;
    const int*   batch = (const int*)d_in[2];
    const float* W1a = (const float*)d_in[3];  const float* b1a = (const float*)d_in[4];
    const float* W2a = (const float*)d_in[5];  const float* b2a = (const float*)d_in[6];
    const float* ga  = (const float*)d_in[7];  const float* bta = (const float*)d_in[8];
    const float* W1b = (const float*)d_in[9];  const float* b1b = (const float*)d_in[10];
    const float* W2b = (const float*)d_in[11]; const float* b2b = (const float*)d_in[12];
    const float* gb  = (const float*)d_in[13]; const float* btb = (const float*)d_in[14];
    const float* lin1_w = (const float*)d_in[15]; const float* lin1_b = (const float*)d_in[16];
    const float* lin2_w = (const float*)d_in[17]; const float* lin2_b = (const float*)d_in[18];
    const float* disc_w = (const float*)d_in[19]; const float* disc_b = (const float*)d_in[20];
    float* outp = (float*)d_out;

    cudaFuncSetAttribute(k_mlp_mma, cudaFuncAttributeMaxDynamicSharedMemorySize, SMEM_BYTES);

    // CSR build + W prep
    k_zero_deg<<<(NN+255)/256, 256>>>();
    k_hist<<<(EE+255)/256, 256>>>(dst);
    k_scan1<<<NB_SCAN, 1024>>>();
    k_scan2<<<1, 128>>>();
    k_scan3<<<(NN+255)/256, 256>>>();
    k_fill<<<(EE+255)/256, 256>>>(src, dst);
    k_gstart<<<1, 96>>>(batch);
    k_wprep<<<768, 256>>>(W1a, W2a, W1b, W2b);
    k_init_affine<<<1, 384>>>();
    k_zero_stats<<<1, 256>>>();

    const int mlp_bx = (NN + 127) / 128;
    const int gather_bx = (NN*32 + 255) / 256;
    const dim3 mlp_grid(mlp_bx, 2);
    const dim3 gather_grid(gather_bx, 2);

    // layer 1 (shared gather of x)
    k_gather1<<<gather_bx, 256>>>(x);
    k_mlp_mma<<<mlp_grid, 256, SMEM_BYTES>>>(1, 0, b1a, b2a, b1b, b2b);
    k_bnfinal2<<<1, 256>>>(ga, bta, gb, btb);

    // layers 2-3
    for (int l = 1; l < 3; l++) {
        k_gather2<<<gather_grid, 256>>>();
        k_mlp_mma<<<mlp_grid, 256, SMEM_BYTES>>>(0, l, b1a, b2a, b1b, b2b);
        k_bnfinal2<<<1, 256>>>(ga + l*HH, bta + l*HH, gb + l*HH, btb + l*HH);
    }

    k_pool2<<<dim3(GG, 2), 128>>>();
    k_head1<<<GG, 128>>>(lin1_w, lin1_b, lin2_w, lin2_b, disc_w, outp);
    k_head2<<<16, 256>>>(disc_b, outp);
}